// round 13
// baseline (speedup 1.0000x reference)
#include <cuda_runtime.h>
#include <math.h>

typedef unsigned long long ull;

#define Bsz 64
#define Tsz 512
#define Esz 256
#define Hsz 512
#define Vsz 128
#define Msz (Bsz*Tsz)   // 32768 rows

// ---------------- scratch (static device arrays; no runtime allocation) -------------
__device__ float g_xw[Msz*Hsz];     // input projection for current layer (t,b,h)
__device__ float g_hs0[Msz*Hsz];    // layer0 hidden states (t,b,h)
__device__ float g_hs1[Msz*Hsz];    // layer1 hidden states (t,b,h)

// ---------------- f32x2 helpers ------------------------------------------------------
__device__ __forceinline__ ull fma2(ull a, ull b, ull c){
    ull d; asm("fma.rn.f32x2 %0, %1, %2, %3;" : "=l"(d) : "l"(a), "l"(b), "l"(c)); return d;
}
__device__ __forceinline__ ull pack2(float x){
    ull d; asm("mov.b64 %0, {%1, %1};" : "=l"(d) : "f"(x)); return d;
}
__device__ __forceinline__ ull packab(float lo, float hi){
    ull d; asm("mov.b64 %0, {%1, %2};" : "=l"(d) : "f"(lo), "f"(hi)); return d;
}
__device__ __forceinline__ void unpack2(ull v, float& lo, float& hi){
    asm("mov.b64 {%0, %1}, %2;" : "=f"(lo), "=f"(hi) : "l"(v));
}

// branch-free tanh: 1 - 2/(e^{2x}+1). MUFU-based, ~5 instr, rel err ~3e-7.
__device__ __forceinline__ float ftanh(float x){
    float e = __expf(2.0f*x);
    return 1.0f - __fdividef(2.0f, e + 1.0f);
}

// ---------------- cluster helpers ----------------------------------------------------
__device__ __forceinline__ unsigned smem_u32(const void* p){
    unsigned a;
    asm("{ .reg .u64 t; cvta.to.shared.u64 t, %1; cvt.u32.u64 %0, t; }" : "=r"(a) : "l"(p));
    return a;
}
__device__ __forceinline__ unsigned mapa_rank(unsigned laddr, unsigned r){
    unsigned ra; asm("mapa.shared::cluster.u32 %0, %1, %2;" : "=r"(ra) : "r"(laddr), "r"(r));
    return ra;
}
__device__ __forceinline__ void cluster_arrive(){
    asm volatile("barrier.cluster.arrive.aligned;" ::: "memory");
}
__device__ __forceinline__ void cluster_wait(){
    asm volatile("barrier.cluster.wait.aligned;"   ::: "memory");
}
__device__ __forceinline__ void mbar_init(unsigned addr, unsigned cnt){
    asm volatile("mbarrier.init.shared.b64 [%0], %1;" :: "r"(addr), "r"(cnt) : "memory");
}
// arm: arrive (count 1) + expect tx bytes for the current phase of own mbar
__device__ __forceinline__ void mbar_expect(unsigned addr, unsigned txb){
    asm volatile("mbarrier.arrive.expect_tx.shared.b64 _, [%0], %1;"
                 :: "r"(addr), "r"(txb) : "memory");
}
// self-signaling remote 8-byte store: data + tx-completion to the SAME remote CTA
__device__ __forceinline__ void st_async64(unsigned raddr, ull v, unsigned rmbar){
    asm volatile("st.async.shared::cluster.mbarrier::complete_tx::bytes.u64 [%0], %1, [%2];"
                 :: "r"(raddr), "l"(v), "r"(rmbar) : "memory");
}
// wait own mbar phase with cluster-scope acquire (orders inbound async stores)
__device__ __forceinline__ void mbar_wait(unsigned addr, unsigned parity){
    asm volatile("{\n\t.reg .pred P;\n\t"
        "W_%=:\n\t"
        "mbarrier.try_wait.parity.acquire.cluster.shared::cta.b64 P, [%0], %1, 0x989680;\n\t"
        "@!P bra W_%=;\n\t}\n"
        :: "r"(addr), "r"(parity) : "memory");
}

// ---------------- kernel: double-buffered fp32 GEMM (R12 winner, unchanged) ---------
// C[M,N] = A[M,K] @ W[N,K]^T + bias
// mode 0: C row-major by A-row.
// mode 1: A-row=(t*B+b) remapped to out[(b*T+t)*N+n] (logits)
// mode 2: A-row gathered through embedding: A[m][k] = emb[x[b*T+t]][k]  (K=Esz)
__global__ void __launch_bounds__(256,2) k_gemm(const float* __restrict__ A,
                                                const float* __restrict__ W,
                                                const float* __restrict__ bias,
                                                float* __restrict__ C,
                                                int M, int N, int K, int mode,
                                                const int* __restrict__ xidx){
    __shared__ __align__(16) float As[2][128*20];   // [m][k], row stride 20 (pad)
    __shared__ __align__(16) float Bs[2][16*130];   // [k][n], row stride 130 (pad)
    const int tid = threadIdx.x;
    const int m0 = blockIdx.x*128;
    const int n0 = blockIdx.y*128;
    const int tx = tid & 15;       // n-group (8 n each)
    const int ty = tid >> 4;       // m-group (8 m each)
    const int mlA = tid >> 2, qA = tid & 3;
    const int nnB = tid & 127, hfB = tid >> 7;
    const int nt = K >> 4;

    // hoisted A/B base pointers (gather index resolved ONCE, not per tile)
    const float* aptr[2];
#pragma unroll
    for (int p=0;p<2;p++){
        int row = m0 + mlA + p*64;
        if (mode == 2){
            int b = row & 63; int tt = row >> 6;
            int v = xidx[b*Tsz + tt];
            aptr[p] = &A[(size_t)v*Esz + qA*4];
        } else {
            aptr[p] = &A[(size_t)row*K + qA*4];
        }
    }
    const float* bptr = &W[(size_t)(n0+nnB)*K + hfB*8];

    ull acc[8][4];
#pragma unroll
    for (int i=0;i<8;i++)
#pragma unroll
        for (int j=0;j<4;j++) acc[i][j] = 0ull;

    float4 ra0, ra1, rb0, rb1;
    // ---- prologue: stage tile 0 ----
    ra0 = *(const float4*)(aptr[0]);
    ra1 = *(const float4*)(aptr[1]);
    rb0 = *(const float4*)(bptr);
    rb1 = *(const float4*)(bptr + 4);
    {
        *(float4*)&As[0][(mlA     )*20 + qA*4] = ra0;
        *(float4*)&As[0][(mlA + 64)*20 + qA*4] = ra1;
        int kb = hfB*8;
        Bs[0][(kb+0)*130+nnB]=rb0.x; Bs[0][(kb+1)*130+nnB]=rb0.y;
        Bs[0][(kb+2)*130+nnB]=rb0.z; Bs[0][(kb+3)*130+nnB]=rb0.w;
        Bs[0][(kb+4)*130+nnB]=rb1.x; Bs[0][(kb+5)*130+nnB]=rb1.y;
        Bs[0][(kb+6)*130+nnB]=rb1.z; Bs[0][(kb+7)*130+nnB]=rb1.w;
    }
    __syncthreads();

    for (int kt=0; kt<nt; kt++){
        const int cur = kt & 1;
        const bool more = (kt+1 < nt);
        if (more){
            int k0 = (kt+1) << 4;
            ra0 = *(const float4*)(aptr[0] + k0);
            ra1 = *(const float4*)(aptr[1] + k0);
            rb0 = *(const float4*)(bptr + k0);
            rb1 = *(const float4*)(bptr + k0 + 4);
        }
        // compute on buffer cur (LDG for next tile in flight)
        const float* Asc = As[cur];
        const float* Bsc = Bs[cur];
#pragma unroll
        for (int kk=0;kk<16;kk++){
            int k = (kk + tx) & 15;                 // per-lane k rotation: kills bank conflicts
            const ull* bp = (const ull*)&Bsc[k*130 + tx*8];
            ull b0=bp[0], b1=bp[1], b2v=bp[2], b3=bp[3];
#pragma unroll
            for (int i=0;i<8;i++){
                ull a2 = pack2(Asc[(ty*8+i)*20 + k]);
                acc[i][0] = fma2(a2, b0,  acc[i][0]);
                acc[i][1] = fma2(a2, b1,  acc[i][1]);
                acc[i][2] = fma2(a2, b2v, acc[i][2]);
                acc[i][3] = fma2(a2, b3,  acc[i][3]);
            }
        }
        if (more){
            const int nxt = cur ^ 1;
            *(float4*)&As[nxt][(mlA     )*20 + qA*4] = ra0;
            *(float4*)&As[nxt][(mlA + 64)*20 + qA*4] = ra1;
            int kb = hfB*8;
            Bs[nxt][(kb+0)*130+nnB]=rb0.x; Bs[nxt][(kb+1)*130+nnB]=rb0.y;
            Bs[nxt][(kb+2)*130+nnB]=rb0.z; Bs[nxt][(kb+3)*130+nnB]=rb0.w;
            Bs[nxt][(kb+4)*130+nnB]=rb1.x; Bs[nxt][(kb+5)*130+nnB]=rb1.y;
            Bs[nxt][(kb+6)*130+nnB]=rb1.z; Bs[nxt][(kb+7)*130+nnB]=rb1.w;
            __syncthreads();
        }
    }
    // epilogue: + bias, write (with optional logits remap)
#pragma unroll
    for (int i=0;i<8;i++){
        int row = m0 + ty*8 + i;
        size_t obase;
        if (mode == 1){ int b = row & 63; int tt = row >> 6; obase = ((size_t)b*Tsz + tt)*(size_t)N; }
        else obase = (size_t)row * (size_t)N;
#pragma unroll
        for (int jn=0;jn<4;jn++){
            int n = n0 + tx*8 + jn*2;
            float2 bv = *(const float2*)&bias[n];
            float lo, hi; unpack2(acc[i][jn], lo, hi);
            float2 o; o.x = lo + bv.x; o.y = hi + bv.y;
            *(float2*)&C[obase + n] = o;
        }
    }
}

// ---------------- kernel: two-stream st.async recurrence, b64-packed fanout ----------
// Protocol identical to R10 champion (per-(stream,slot) tx-mbarriers, TXB=4096 bytes,
// same arm/parity/guard schedule, t=511 pushes nothing). ONLY the reduce tail and the
// fanout width change:
//   - select-fold lane bits 8,4; then PURE butterfly folds over bits 2,1 on BOTH
//     kept values -> each lane ends with outputs (j2, j2+1) fully reduced, where
//     j2 = j0 + 2*((kq>>2)&1), b = kq>>3; replicated across the 4 lanes of sub=kq&3.
//   - pack the pair into u64; sub-lane s pushes st.async.b64 to ranks {2s, 2s+1}.
// Transactions: 4 st.async/thread/step (was 8), 1024 inbound/CTA/step (was 2048) --
// halves the DSMEM port serialization that dominated the residual per-step time.
#define CH   36                    // 32 floats + 4 pad per k-slice
#define HB   (2*16*CH)             // 2 batches x 16 slices = 1152 floats per region
#define HB4  (HB*4)                // bytes per region
#define TXB  4096u                 // inbound bytes per mbar phase: 1024 floats

__global__ void __launch_bounds__(256,1) __cluster_dims__(8,1,1)
k_rnn(const float* __restrict__ xw, float* __restrict__ hs,
      const float* __restrict__ Whh, float* __restrict__ hlast){
    __shared__ __align__(16) float sh[4*HB];             // region = stream*2 + slot
    __shared__ __align__(8) ull mb[4];                   // mbar per region
    const int cl   = blockIdx.x >> 3;
    const int rank = blockIdx.x & 7;
    const int tid  = threadIdx.x;
    const int w    = tid >> 5;
    const int lane = tid & 31;
    const int jq   = lane >> 4;
    const int kq   = lane & 15;
    const int j0   = rank*64 + w*8 + jq*4;
    const int bw   = kq >> 3;                // batch within stream
    const int jhalf= (kq >> 2) & 1;
    const int sub  = kq & 3;                 // fanout sub-group -> ranks {2sub, 2sub+1}
    const int j2   = j0 + 2*jhalf;           // this lane's output PAIR base (j2, j2+1)
    const bool stl = (sub == 0);             // sub 0 does the global float2 stores
    const int bA   = cl*4 + bw;              // absolute batch, stream A
    const int bB   = cl*4 + 2 + bw;          // absolute batch, stream B
    const int BH   = Bsz*Hsz;

    // ---- weights: W_hh[j0+jj][kq*32 .. +32) as 16 f32x2 each (serve both streams) ----
    ull w2[4][16];
#pragma unroll
    for (int jj=0;jj<4;jj++){
        const ull* wp = (const ull*)(Whh + (size_t)(j0+jj)*Hsz + kq*32);
#pragma unroll
        for (int i=0;i<16;i++) w2[jj][i] = wp[i];
    }

    // ---- mbar init, cluster-wide visibility, then arm phase 0 of all 4 ----
    const unsigned mb_base = smem_u32(mb);
    if (tid == 0){
#pragma unroll
        for (int i=0;i<4;i++) mbar_init(mb_base + i*8, 1u);
    }
    __syncthreads();
    cluster_arrive(); cluster_wait();        // inits visible before any inbound st.async
    if (tid == 0){
#pragma unroll
        for (int i=0;i<4;i++) mbar_expect(mb_base + i*8, TXB);
    }

    // ---- DSMEM push addresses: sub-lane s -> ranks 2s, 2s+1 ----
    const unsigned sbase = smem_u32(sh);
    const unsigned rs0 = mapa_rank(sbase,   2*sub);
    const unsigned rs1 = mapa_rank(sbase,   2*sub+1);
    const unsigned rm0 = mapa_rank(mb_base, 2*sub);
    const unsigned rm1 = mapa_rank(mb_base, 2*sub+1);
    // consumer layout within a region: ((b*16 + (k>>5))*CH + (k&31))*4; our k = j2 (even)
    const unsigned inner = (unsigned)(((bw*16 + (j2>>5))*CH + (j2&31))*4);   // 8B aligned

    const float* xwpA = xw + (size_t)bA*Hsz + j2;
    const float* xwpB = xw + (size_t)bB*Hsz + j2;
    float*       hspA = hs + (size_t)bA*Hsz + j2;
    float*       hspB = hs + (size_t)bB*Hsz + j2;

    const bool hi8 = (lane & 8) != 0;
    const bool hi4 = (lane & 4) != 0;

    // per-stream FMA+reduce over region bi -> output pair (j2, j2+1)
    auto stream_mv = [&](int bi, float& o0, float& o1){
        const float* buf = sh + bi*HB;
        ull acc[2][4];
#pragma unroll
        for (int b=0;b<2;b++)
#pragma unroll
            for (int jj=0;jj<4;jj++) acc[b][jj] = 0ull;
#pragma unroll
        for (int b=0;b<2;b++){
            const ull* hq = (const ull*)(buf + (b*16 + kq)*CH);
#pragma unroll
            for (int kk=0;kk<16;kk+=2){
                ulonglong2 p = *(const ulonglong2*)&hq[kk];
#pragma unroll
                for (int jj=0;jj<4;jj++){
                    acc[b][jj] = fma2(p.x, w2[jj][kk],   acc[b][jj]);
                    acc[b][jj] = fma2(p.y, w2[jj][kk+1], acc[b][jj]);
                }
            }
        }
        float v[8];
#pragma unroll
        for (int b=0;b<2;b++)
#pragma unroll
            for (int jj=0;jj<4;jj++){
                float l, h; unpack2(acc[b][jj], l, h);
                v[b*4+jj] = l + h;
            }
        // select-fold bit 8: v[0..3] -> (b = hi8, jj = o)
#pragma unroll
        for (int o=0;o<4;o++){
            float keepv = hi8 ? v[o+4] : v[o];
            float sendv = hi8 ? v[o]   : v[o+4];
            v[o] = keepv + __shfl_xor_sync(0xffffffffu, sendv, 8);
        }
        // select-fold bit 4: v[0..1] -> (b = hi8, jj = 2*hi4 + o)
#pragma unroll
        for (int o=0;o<2;o++){
            float keepv = hi4 ? v[o+2] : v[o];
            float sendv = hi4 ? v[o]   : v[o+2];
            v[o] = keepv + __shfl_xor_sync(0xffffffffu, sendv, 4);
        }
        // pure butterfly folds over remaining k bits 2, 1 (outputs unchanged)
        v[0] += __shfl_xor_sync(0xffffffffu, v[0], 2);
        v[1] += __shfl_xor_sync(0xffffffffu, v[1], 2);
        v[0] += __shfl_xor_sync(0xffffffffu, v[0], 1);
        v[1] += __shfl_xor_sync(0xffffffffu, v[1], 1);
        o0 = v[0]; o1 = v[1];
    };

    // push the packed output pair to this lane's 2 ranks (self-signaling b64 stores)
    auto push_async = [&](float h0, float h1, int region){
        ull pk = packab(h0, h1);
        unsigned woff = (unsigned)(region*HB4) + inner;
        unsigned moff = (unsigned)(region*8);
        st_async64(rs0 + woff, pk, rm0 + moff);
        st_async64(rs1 + woff, pk, rm1 + moff);
    };

    // ---- t = 0 (h_prev = 0) ----
    float2 xwA = *(const float2*)xwpA;
    float2 xwB = *(const float2*)xwpB;
    {
        float a0 = ftanh(xwA.x), a1 = ftanh(xwA.y);
        if (stl){ float2 o; o.x=a0; o.y=a1; *(float2*)hspA = o; }
        push_async(a0, a1, 0);               // stream A, slot 0
        float b0 = ftanh(xwB.x), b1 = ftanh(xwB.y);
        if (stl){ float2 o; o.x=b0; o.y=b1; *(float2*)hspB = o; }
        push_async(b0, b1, 2);               // stream B, slot 0
    }
    xwA = *(const float2*)(xwpA + BH);
    xwB = *(const float2*)(xwpB + BH);       // prefetch t=1

    for (int t=1;t<Tsz;t++){
        const int m   = (t-1) & 1;                       // mbar/buffer slot of h[t-1]
        const unsigned par = (unsigned)(((t-1) >> 1) & 1);
        const int slot = t & 1;                          // slot for h[t]
        const int toff = t << 15;                        // t*BH

        // ---------- stream A ----------
        mbar_wait(mb_base + (0*2+m)*8, par);             // h[t-1] of A complete
        if (tid == 0 && t <= 509) mbar_expect(mb_base + (0*2+m)*8, TXB);  // arm h[t+1]
        float sA0, sA1; stream_mv(0*2 + m, sA0, sA1);
        float hA0 = ftanh(sA0 + xwA.x);
        float hA1 = ftanh(sA1 + xwA.y);
        if (stl){ float2 o; o.x=hA0; o.y=hA1; *(float2*)(hspA + toff) = o; }
        if (t <= 510) push_async(hA0, hA1, 0*2 + slot);
        if (t != Tsz-1) xwA = *(const float2*)(xwpA + toff + BH);   // hides under B
        else if (stl){ float2 o; o.x=hA0; o.y=hA1; *(float2*)(hlast + (size_t)bA*Hsz + j2) = o; }

        // ---------- stream B ----------
        mbar_wait(mb_base + (1*2+m)*8, par);             // h[t-1] of B complete
        if (tid == 0 && t <= 509) mbar_expect(mb_base + (1*2+m)*8, TXB);
        float sB0, sB1; stream_mv(1*2 + m, sB0, sB1);
        float hB0 = ftanh(sB0 + xwB.x);
        float hB1 = ftanh(sB1 + xwB.y);
        if (stl){ float2 o; o.x=hB0; o.y=hB1; *(float2*)(hspB + toff) = o; }
        if (t <= 510) push_async(hB0, hB1, 1*2 + slot);
        if (t != Tsz-1) xwB = *(const float2*)(xwpB + toff + BH);
        else if (stl){ float2 o; o.x=hB0; o.y=hB1; *(float2*)(hlast + (size_t)bB*Hsz + j2) = o; }
    }
    // no drain needed: t=511 pushed nothing; final waits consumed all inbound tx
}

// ---------------- launch -------------------------------------------------------------
extern "C" void kernel_launch(void* const* d_in, const int* in_sizes, int n_in,
                              void* d_out, int out_size){
    const int*   x    = (const int*)  d_in[0];
    const float* emb  = (const float*)d_in[1];
    const float* Wxh0 = (const float*)d_in[2];
    const float* Whh0 = (const float*)d_in[3];
    const float* bh0  = (const float*)d_in[4];
    const float* Wxh1 = (const float*)d_in[5];
    const float* Whh1 = (const float*)d_in[6];
    const float* bh1  = (const float*)d_in[7];
    const float* Why  = (const float*)d_in[8];
    const float* by   = (const float*)d_in[9];
    float* out = (float*)d_out;

    float *xwbuf, *hs0, *hs1;
    cudaGetSymbolAddress((void**)&xwbuf, g_xw);
    cudaGetSymbolAddress((void**)&hs0,   g_hs0);
    cudaGetSymbolAddress((void**)&hs1,   g_hs1);

    const size_t LOGITS = (size_t)Bsz*Tsz*Vsz;   // 4194304

    dim3 gH(Msz/128, Hsz/128);

    // 1) xw0 = gather(emb, x) @ Wxh0^T + bh0   (gather fused into A-load)
    k_gemm<<<gH, 256>>>(emb, Wxh0, bh0, xwbuf, Msz, Hsz, Esz, 2, x);

    // 2) layer-0 recurrence -> hs0, h_last0
    k_rnn<<<128, 256>>>(xwbuf, hs0, Whh0, out + LOGITS);

    // 3) xw1 = hs0 @ Wxh1^T + bh1
    k_gemm<<<gH, 256>>>(hs0, Wxh1, bh1, xwbuf, Msz, Hsz, Hsz, 0, 0);

    // 4) layer-1 recurrence -> hs1, h_last1
    k_rnn<<<128, 256>>>(xwbuf, hs1, Whh1, out + LOGITS + (size_t)Bsz*Hsz);

    // 5) logits = hs1 @ Why^T + by  (remapped to (b,t,v))
    dim3 gV(Msz/128, Vsz/128);
    k_gemm<<<gV, 256>>>(hs1, Why, by, out, Msz, Vsz, Hsz, 1, 0);
}

// round 14
// speedup vs baseline: 1.0165x; 1.0165x over previous
#include <cuda_runtime.h>
#include <math.h>

typedef unsigned long long ull;

#define Bsz 64
#define Tsz 512
#define Esz 256
#define Hsz 512
#define Vsz 128
#define Msz (Bsz*Tsz)   // 32768 rows

// ---------------- scratch (static device arrays; no runtime allocation) -------------
__device__ float g_xw[Msz*Hsz];     // input projection for current layer (t,b,h)
__device__ float g_hs0[Msz*Hsz];    // layer0 hidden states (t,b,h)
__device__ float g_hs1[Msz*Hsz];    // layer1 hidden states (t,b,h)

// ---------------- f32x2 helpers ------------------------------------------------------
__device__ __forceinline__ ull fma2(ull a, ull b, ull c){
    ull d; asm("fma.rn.f32x2 %0, %1, %2, %3;" : "=l"(d) : "l"(a), "l"(b), "l"(c)); return d;
}
__device__ __forceinline__ ull pack2(float x){
    ull d; asm("mov.b64 %0, {%1, %1};" : "=l"(d) : "f"(x)); return d;
}
__device__ __forceinline__ void unpack2(ull v, float& lo, float& hi){
    asm("mov.b64 {%0, %1}, %2;" : "=f"(lo), "=f"(hi) : "l"(v));
}

// branch-free tanh: 1 - 2/(e^{2x}+1). MUFU-based, ~5 instr, rel err ~3e-7.
__device__ __forceinline__ float ftanh(float x){
    float e = __expf(2.0f*x);
    return 1.0f - __fdividef(2.0f, e + 1.0f);
}

// ---------------- cluster helpers ----------------------------------------------------
__device__ __forceinline__ unsigned smem_u32(const void* p){
    unsigned a;
    asm("{ .reg .u64 t; cvta.to.shared.u64 t, %1; cvt.u32.u64 %0, t; }" : "=r"(a) : "l"(p));
    return a;
}
__device__ __forceinline__ unsigned mapa_rank(unsigned laddr, unsigned r){
    unsigned ra; asm("mapa.shared::cluster.u32 %0, %1, %2;" : "=r"(ra) : "r"(laddr), "r"(r));
    return ra;
}
__device__ __forceinline__ void cluster_arrive(){
    asm volatile("barrier.cluster.arrive.aligned;" ::: "memory");
}
__device__ __forceinline__ void cluster_wait(){
    asm volatile("barrier.cluster.wait.aligned;"   ::: "memory");
}
__device__ __forceinline__ void mbar_init(unsigned addr, unsigned cnt){
    asm volatile("mbarrier.init.shared.b64 [%0], %1;" :: "r"(addr), "r"(cnt) : "memory");
}
// arm: arrive (count 1) + expect tx bytes for the current phase of own mbar
__device__ __forceinline__ void mbar_expect(unsigned addr, unsigned txb){
    asm volatile("mbarrier.arrive.expect_tx.shared.b64 _, [%0], %1;"
                 :: "r"(addr), "r"(txb) : "memory");
}
// self-signaling remote store: data + tx-completion both to the SAME remote CTA
__device__ __forceinline__ void st_async(unsigned raddr, float v, unsigned rmbar){
    asm volatile("st.async.shared::cluster.mbarrier::complete_tx::bytes.u32 [%0], %1, [%2];"
                 :: "r"(raddr), "r"(__float_as_uint(v)), "r"(rmbar) : "memory");
}
// wait own mbar phase with cluster-scope acquire (orders inbound async stores)
__device__ __forceinline__ void mbar_wait(unsigned addr, unsigned parity){
    asm volatile("{\n\t.reg .pred P;\n\t"
        "W_%=:\n\t"
        "mbarrier.try_wait.parity.acquire.cluster.shared::cta.b64 P, [%0], %1, 0x989680;\n\t"
        "@!P bra W_%=;\n\t}\n"
        :: "r"(addr), "r"(parity) : "memory");
}

// ---------------- kernel: double-buffered fp32 GEMM (R12 winner, unchanged) ---------
// C[M,N] = A[M,K] @ W[N,K]^T + bias
// mode 0: C row-major by A-row.
// mode 1: A-row=(t*B+b) remapped to out[(b*T+t)*N+n] (logits)
// mode 2: A-row gathered through embedding: A[m][k] = emb[x[b*T+t]][k]  (K=Esz)
__global__ void __launch_bounds__(256,2) k_gemm(const float* __restrict__ A,
                                                const float* __restrict__ W,
                                                const float* __restrict__ bias,
                                                float* __restrict__ C,
                                                int M, int N, int K, int mode,
                                                const int* __restrict__ xidx){
    __shared__ __align__(16) float As[2][128*20];   // [m][k], row stride 20 (pad)
    __shared__ __align__(16) float Bs[2][16*130];   // [k][n], row stride 130 (pad)
    const int tid = threadIdx.x;
    const int m0 = blockIdx.x*128;
    const int n0 = blockIdx.y*128;
    const int tx = tid & 15;       // n-group (8 n each)
    const int ty = tid >> 4;       // m-group (8 m each)
    const int mlA = tid >> 2, qA = tid & 3;
    const int nnB = tid & 127, hfB = tid >> 7;
    const int nt = K >> 4;

    // hoisted A/B base pointers (gather index resolved ONCE, not per tile)
    const float* aptr[2];
#pragma unroll
    for (int p=0;p<2;p++){
        int row = m0 + mlA + p*64;
        if (mode == 2){
            int b = row & 63; int tt = row >> 6;
            int v = xidx[b*Tsz + tt];
            aptr[p] = &A[(size_t)v*Esz + qA*4];
        } else {
            aptr[p] = &A[(size_t)row*K + qA*4];
        }
    }
    const float* bptr = &W[(size_t)(n0+nnB)*K + hfB*8];

    ull acc[8][4];
#pragma unroll
    for (int i=0;i<8;i++)
#pragma unroll
        for (int j=0;j<4;j++) acc[i][j] = 0ull;

    float4 ra0, ra1, rb0, rb1;
    // ---- prologue: stage tile 0 ----
    ra0 = *(const float4*)(aptr[0]);
    ra1 = *(const float4*)(aptr[1]);
    rb0 = *(const float4*)(bptr);
    rb1 = *(const float4*)(bptr + 4);
    {
        *(float4*)&As[0][(mlA     )*20 + qA*4] = ra0;
        *(float4*)&As[0][(mlA + 64)*20 + qA*4] = ra1;
        int kb = hfB*8;
        Bs[0][(kb+0)*130+nnB]=rb0.x; Bs[0][(kb+1)*130+nnB]=rb0.y;
        Bs[0][(kb+2)*130+nnB]=rb0.z; Bs[0][(kb+3)*130+nnB]=rb0.w;
        Bs[0][(kb+4)*130+nnB]=rb1.x; Bs[0][(kb+5)*130+nnB]=rb1.y;
        Bs[0][(kb+6)*130+nnB]=rb1.z; Bs[0][(kb+7)*130+nnB]=rb1.w;
    }
    __syncthreads();

    for (int kt=0; kt<nt; kt++){
        const int cur = kt & 1;
        const bool more = (kt+1 < nt);
        if (more){
            int k0 = (kt+1) << 4;
            ra0 = *(const float4*)(aptr[0] + k0);
            ra1 = *(const float4*)(aptr[1] + k0);
            rb0 = *(const float4*)(bptr + k0);
            rb1 = *(const float4*)(bptr + k0 + 4);
        }
        // compute on buffer cur (LDG for next tile in flight)
        const float* Asc = As[cur];
        const float* Bsc = Bs[cur];
#pragma unroll
        for (int kk=0;kk<16;kk++){
            int k = (kk + tx) & 15;                 // per-lane k rotation: kills bank conflicts
            const ull* bp = (const ull*)&Bsc[k*130 + tx*8];
            ull b0=bp[0], b1=bp[1], b2v=bp[2], b3=bp[3];
#pragma unroll
            for (int i=0;i<8;i++){
                ull a2 = pack2(Asc[(ty*8+i)*20 + k]);
                acc[i][0] = fma2(a2, b0,  acc[i][0]);
                acc[i][1] = fma2(a2, b1,  acc[i][1]);
                acc[i][2] = fma2(a2, b2v, acc[i][2]);
                acc[i][3] = fma2(a2, b3,  acc[i][3]);
            }
        }
        if (more){
            const int nxt = cur ^ 1;
            *(float4*)&As[nxt][(mlA     )*20 + qA*4] = ra0;
            *(float4*)&As[nxt][(mlA + 64)*20 + qA*4] = ra1;
            int kb = hfB*8;
            Bs[nxt][(kb+0)*130+nnB]=rb0.x; Bs[nxt][(kb+1)*130+nnB]=rb0.y;
            Bs[nxt][(kb+2)*130+nnB]=rb0.z; Bs[nxt][(kb+3)*130+nnB]=rb0.w;
            Bs[nxt][(kb+4)*130+nnB]=rb1.x; Bs[nxt][(kb+5)*130+nnB]=rb1.y;
            Bs[nxt][(kb+6)*130+nnB]=rb1.z; Bs[nxt][(kb+7)*130+nnB]=rb1.w;
            __syncthreads();
        }
    }
    // epilogue: + bias, write (with optional logits remap)
#pragma unroll
    for (int i=0;i<8;i++){
        int row = m0 + ty*8 + i;
        size_t obase;
        if (mode == 1){ int b = row & 63; int tt = row >> 6; obase = ((size_t)b*Tsz + tt)*(size_t)N; }
        else obase = (size_t)row * (size_t)N;
#pragma unroll
        for (int jn=0;jn<4;jn++){
            int n = n0 + tx*8 + jn*2;
            float2 bv = *(const float2*)&bias[n];
            float lo, hi; unpack2(acc[i][jn], lo, hi);
            float2 o; o.x = lo + bv.x; o.y = hi + bv.y;
            *(float2*)&C[obase + n] = o;
        }
    }
}

// ---------------- kernel: two-stream st.async recurrence, FUSED segments -------------
// Protocol identical to R10/R12 champion (per-(stream,slot) tx-mbarriers, TXB=4096,
// same arm/parity/guard schedule, 4-rank b32 fanout, t=511 pushes nothing).
// ONLY the loop-body ordering changes: both waits are issued up front (their data is
// a full step old -> near-free), then streams A and B are computed REGISTER-INTERLEAVED
// (16 independent FMA chains; the two shuffle-reduce trees' stages alternate so their
// ~26cyc latencies overlap; both tanhs together; both pushes at the end). This removes
// one full exposed serial chain (LDS lat + reduce tree + tanh + push tail) per step.
#define CH   36                    // 32 floats + 4 pad per k-slice
#define HB   (2*16*CH)             // 2 batches x 16 slices = 1152 floats per region
#define HB4  (HB*4)                // bytes per region
#define TXB  4096u                 // inbound bytes per mbar phase: 1024 floats

__global__ void __launch_bounds__(256,1) __cluster_dims__(8,1,1)
k_rnn(const float* __restrict__ xw, float* __restrict__ hs,
      const float* __restrict__ Whh, float* __restrict__ hlast){
    __shared__ __align__(16) float sh[4*HB];             // region = stream*2 + slot
    __shared__ __align__(8) ull mb[4];                   // mbar per region
    const int cl   = blockIdx.x >> 3;
    const int rank = blockIdx.x & 7;
    const int tid  = threadIdx.x;
    const int w    = tid >> 5;
    const int lane = tid & 31;
    const int jq   = lane >> 4;
    const int kq   = lane & 15;
    const int j0   = rank*64 + w*8 + jq*4;
    const int bw   = (kq >> 3) & 1;          // batch within stream
    const int j_out= j0 + ((kq >> 1) & 3);
    const int odd  = kq & 1;
    const int bA   = cl*4 + bw;              // absolute batch, stream A output
    const int bB   = cl*4 + 2 + bw;          // absolute batch, stream B output
    const int BH   = Bsz*Hsz;

    // ---- weights: W_hh[j0+jj][kq*32 .. +32) as 16 f32x2 each (serve both streams) ----
    ull w2[4][16];
#pragma unroll
    for (int jj=0;jj<4;jj++){
        const ull* wp = (const ull*)(Whh + (size_t)(j0+jj)*Hsz + kq*32);
#pragma unroll
        for (int i=0;i<16;i++) w2[jj][i] = wp[i];
    }

    // ---- mbar init, cluster-wide visibility, then arm phase 0 of all 4 ----
    const unsigned mb_base = smem_u32(mb);
    if (tid == 0){
#pragma unroll
        for (int i=0;i<4;i++) mbar_init(mb_base + i*8, 1u);
    }
    __syncthreads();
    cluster_arrive(); cluster_wait();        // inits visible before any inbound st.async
    if (tid == 0){
#pragma unroll
        for (int i=0;i<4;i++) mbar_expect(mb_base + i*8, TXB);
    }

    // ---- DSMEM push addresses (data + mbar, SAME 4 ranks) ----
    const unsigned sbase = smem_u32(sh);
    unsigned rsh[4], rmb[4];
#pragma unroll
    for (int r=0;r<4;r++){
        rsh[r] = mapa_rank(sbase,   odd*4 + r);
        rmb[r] = mapa_rank(mb_base, odd*4 + r);
    }
    // consumer layout within a region: ((b*16 + (k>>5))*CH + (k&31)); our k = j_out
    const unsigned inner = (unsigned)(((bw*16 + (j_out>>5))*CH + (j_out&31))*4);

    const float* xwpA = xw + (size_t)bA*Hsz + j_out;
    const float* xwpB = xw + (size_t)bB*Hsz + j_out;
    float*       hspA = hs + (size_t)bA*Hsz + j_out;
    float*       hspB = hs + (size_t)bB*Hsz + j_out;

    const bool hi8 = (lane & 8) != 0;
    const bool hi4 = (lane & 4) != 0;
    const bool hi2 = (lane & 2) != 0;

    // push one output to 4 ranks, each store self-signals that rank's region mbar
    auto push_async = [&](float hv, int region){
        unsigned woff = (unsigned)(region*HB4) + inner;
        unsigned moff = (unsigned)(region*8);
#pragma unroll
        for (int r=0;r<4;r++) st_async(rsh[r] + woff, hv, rmb[r] + moff);
    };

    // ---- t = 0 (h_prev = 0) ----
    float xwA = xwpA[0], xwB = xwpB[0];
    {
        float hvA = ftanh(xwA);
        if (!odd) hspA[0] = hvA;
        push_async(hvA, 0);                  // stream A, slot 0
        float hvB = ftanh(xwB);
        if (odd) hspB[0] = hvB;
        push_async(hvB, 2);                  // stream B, slot 0
    }
    xwA = xwpA[BH];  xwB = xwpB[BH];         // prefetch t=1

    for (int t=1;t<Tsz;t++){
        const int m   = (t-1) & 1;                       // mbar/buffer slot of h[t-1]
        const unsigned par = (unsigned)(((t-1) >> 1) & 1);
        const int slot = t & 1;                          // slot for h[t]
        const int toff = t << 15;                        // t*BH

        // ---- both waits up front (data is a full step old -> near-free) ----
        mbar_wait(mb_base + (0*2+m)*8, par);             // h[t-1] of A complete
        if (tid == 0 && t <= 509) mbar_expect(mb_base + (0*2+m)*8, TXB);
        mbar_wait(mb_base + (1*2+m)*8, par);             // h[t-1] of B complete
        if (tid == 0 && t <= 509) mbar_expect(mb_base + (1*2+m)*8, TXB);

        // ---- fused interleaved FMA: 16 independent accumulator chains ----
        const float* bufA = sh + (0*2+m)*HB;
        const float* bufB = sh + (1*2+m)*HB;
        ull accA[2][4], accB[2][4];
#pragma unroll
        for (int b=0;b<2;b++)
#pragma unroll
            for (int jj=0;jj<4;jj++){ accA[b][jj]=0ull; accB[b][jj]=0ull; }
#pragma unroll
        for (int b=0;b<2;b++){
            const ull* hqA = (const ull*)(bufA + (b*16 + kq)*CH);
            const ull* hqB = (const ull*)(bufB + (b*16 + kq)*CH);
#pragma unroll
            for (int kk=0;kk<16;kk+=2){
                ulonglong2 pA = *(const ulonglong2*)&hqA[kk];
                ulonglong2 pB = *(const ulonglong2*)&hqB[kk];
#pragma unroll
                for (int jj=0;jj<4;jj++){
                    accA[b][jj] = fma2(pA.x, w2[jj][kk],   accA[b][jj]);
                    accA[b][jj] = fma2(pA.y, w2[jj][kk+1], accA[b][jj]);
                    accB[b][jj] = fma2(pB.x, w2[jj][kk],   accB[b][jj]);
                    accB[b][jj] = fma2(pB.y, w2[jj][kk+1], accB[b][jj]);
                }
            }
        }
        // collapse f32x2 -> scalars
        float vA[8], vB[8];
#pragma unroll
        for (int b=0;b<2;b++)
#pragma unroll
            for (int jj=0;jj<4;jj++){
                float l, h;
                unpack2(accA[b][jj], l, h); vA[b*4+jj] = l + h;
                unpack2(accB[b][jj], l, h); vB[b*4+jj] = l + h;
            }
        // interleaved butterfly reduce trees (A/B stages alternate -> latencies overlap)
#pragma unroll
        for (int o=0;o<4;o++){
            float kA = hi8 ? vA[o+4] : vA[o];
            float sA = hi8 ? vA[o]   : vA[o+4];
            float kB = hi8 ? vB[o+4] : vB[o];
            float sB = hi8 ? vB[o]   : vB[o+4];
            vA[o] = kA + __shfl_xor_sync(0xffffffffu, sA, 8);
            vB[o] = kB + __shfl_xor_sync(0xffffffffu, sB, 8);
        }
#pragma unroll
        for (int o=0;o<2;o++){
            float kA = hi4 ? vA[o+2] : vA[o];
            float sA = hi4 ? vA[o]   : vA[o+2];
            float kB = hi4 ? vB[o+2] : vB[o];
            float sB = hi4 ? vB[o]   : vB[o+2];
            vA[o] = kA + __shfl_xor_sync(0xffffffffu, sA, 4);
            vB[o] = kB + __shfl_xor_sync(0xffffffffu, sB, 4);
        }
        {
            float kA = hi2 ? vA[1] : vA[0];
            float sA = hi2 ? vA[0] : vA[1];
            float kB = hi2 ? vB[1] : vB[0];
            float sB = hi2 ? vB[0] : vB[1];
            vA[0] = kA + __shfl_xor_sync(0xffffffffu, sA, 2);
            vB[0] = kB + __shfl_xor_sync(0xffffffffu, sB, 2);
        }
        vA[0] += __shfl_xor_sync(0xffffffffu, vA[0], 1);
        vB[0] += __shfl_xor_sync(0xffffffffu, vB[0], 1);

        float hvA = ftanh(vA[0] + xwA);
        float hvB = ftanh(vB[0] + xwB);
        if (!odd) hspA[toff] = hvA;
        else      hspB[toff] = hvB;
        if (t <= 510){
            push_async(hvA, 0*2 + slot);
            push_async(hvB, 1*2 + slot);
        }
        if (t != Tsz-1){
            xwA = xwpA[toff + BH];                       // prefetch next step
            xwB = xwpB[toff + BH];
        } else {
            if (!odd) hlast[bA*Hsz + j_out] = hvA;
            else      hlast[bB*Hsz + j_out] = hvB;
        }
    }
    // no drain needed: t=511 pushed nothing; final waits consumed all inbound tx
}

// ---------------- launch -------------------------------------------------------------
extern "C" void kernel_launch(void* const* d_in, const int* in_sizes, int n_in,
                              void* d_out, int out_size){
    const int*   x    = (const int*)  d_in[0];
    const float* emb  = (const float*)d_in[1];
    const float* Wxh0 = (const float*)d_in[2];
    const float* Whh0 = (const float*)d_in[3];
    const float* bh0  = (const float*)d_in[4];
    const float* Wxh1 = (const float*)d_in[5];
    const float* Whh1 = (const float*)d_in[6];
    const float* bh1  = (const float*)d_in[7];
    const float* Why  = (const float*)d_in[8];
    const float* by   = (const float*)d_in[9];
    float* out = (float*)d_out;

    float *xwbuf, *hs0, *hs1;
    cudaGetSymbolAddress((void**)&xwbuf, g_xw);
    cudaGetSymbolAddress((void**)&hs0,   g_hs0);
    cudaGetSymbolAddress((void**)&hs1,   g_hs1);

    const size_t LOGITS = (size_t)Bsz*Tsz*Vsz;   // 4194304

    dim3 gH(Msz/128, Hsz/128);

    // 1) xw0 = gather(emb, x) @ Wxh0^T + bh0   (gather fused into A-load)
    k_gemm<<<gH, 256>>>(emb, Wxh0, bh0, xwbuf, Msz, Hsz, Esz, 2, x);

    // 2) layer-0 recurrence -> hs0, h_last0
    k_rnn<<<128, 256>>>(xwbuf, hs0, Whh0, out + LOGITS);

    // 3) xw1 = hs0 @ Wxh1^T + bh1
    k_gemm<<<gH, 256>>>(hs0, Wxh1, bh1, xwbuf, Msz, Hsz, Hsz, 0, 0);

    // 4) layer-1 recurrence -> hs1, h_last1
    k_rnn<<<128, 256>>>(xwbuf, hs1, Whh1, out + LOGITS + (size_t)Bsz*Hsz);

    // 5) logits = hs1 @ Why^T + by  (remapped to (b,t,v))
    dim3 gV(Msz/128, Vsz/128);
    k_gemm<<<gV, 256>>>(hs1, Why, by, out, Msz, Vsz, Hsz, 1, 0);
}

// round 15
// speedup vs baseline: 1.0295x; 1.0128x over previous
#include <cuda_runtime.h>
#include <math.h>

typedef unsigned long long ull;

#define Bsz 64
#define Tsz 512
#define Esz 256
#define Hsz 512
#define Vsz 128
#define Msz (Bsz*Tsz)   // 32768 rows

// ---------------- scratch (static device arrays; no runtime allocation) -------------
__device__ float g_xw[Msz*Hsz];     // input projection for current layer (t,b,h)
__device__ float g_hs0[Msz*Hsz];    // layer0 hidden states (t,b,h)
__device__ float g_hs1[Msz*Hsz];    // layer1 hidden states (t,b,h)

// ---------------- f32x2 helpers ------------------------------------------------------
__device__ __forceinline__ ull fma2(ull a, ull b, ull c){
    ull d; asm("fma.rn.f32x2 %0, %1, %2, %3;" : "=l"(d) : "l"(a), "l"(b), "l"(c)); return d;
}
__device__ __forceinline__ ull pack2(float x){
    ull d; asm("mov.b64 %0, {%1, %1};" : "=l"(d) : "f"(x)); return d;
}
__device__ __forceinline__ void unpack2(ull v, float& lo, float& hi){
    asm("mov.b64 {%0, %1}, %2;" : "=f"(lo), "=f"(hi) : "l"(v));
}

// branch-free tanh: 1 - 2/(e^{2x}+1). MUFU-based, ~5 instr, rel err ~3e-7.
__device__ __forceinline__ float ftanh(float x){
    float e = __expf(2.0f*x);
    return 1.0f - __fdividef(2.0f, e + 1.0f);
}

// ---------------- cluster helpers ----------------------------------------------------
__device__ __forceinline__ unsigned smem_u32(const void* p){
    unsigned a;
    asm("{ .reg .u64 t; cvta.to.shared.u64 t, %1; cvt.u32.u64 %0, t; }" : "=r"(a) : "l"(p));
    return a;
}
__device__ __forceinline__ unsigned mapa_rank(unsigned laddr, unsigned r){
    unsigned ra; asm("mapa.shared::cluster.u32 %0, %1, %2;" : "=r"(ra) : "r"(laddr), "r"(r));
    return ra;
}
__device__ __forceinline__ void cluster_arrive(){
    asm volatile("barrier.cluster.arrive.aligned;" ::: "memory");
}
__device__ __forceinline__ void cluster_wait(){
    asm volatile("barrier.cluster.wait.aligned;"   ::: "memory");
}
__device__ __forceinline__ void mbar_init(unsigned addr, unsigned cnt){
    asm volatile("mbarrier.init.shared.b64 [%0], %1;" :: "r"(addr), "r"(cnt) : "memory");
}
// arm: arrive (count 1) + expect tx bytes for the current phase of own mbar
__device__ __forceinline__ void mbar_expect(unsigned addr, unsigned txb){
    asm volatile("mbarrier.arrive.expect_tx.shared.b64 _, [%0], %1;"
                 :: "r"(addr), "r"(txb) : "memory");
}
// self-signaling remote store: data + tx-completion both to the SAME remote CTA
__device__ __forceinline__ void st_async(unsigned raddr, float v, unsigned rmbar){
    asm volatile("st.async.shared::cluster.mbarrier::complete_tx::bytes.u32 [%0], %1, [%2];"
                 :: "r"(raddr), "r"(__float_as_uint(v)), "r"(rmbar) : "memory");
}
// wait own mbar phase with cluster-scope acquire (orders inbound async stores)
__device__ __forceinline__ void mbar_wait(unsigned addr, unsigned parity){
    asm volatile("{\n\t.reg .pred P;\n\t"
        "W_%=:\n\t"
        "mbarrier.try_wait.parity.acquire.cluster.shared::cta.b64 P, [%0], %1, 0x989680;\n\t"
        "@!P bra W_%=;\n\t}\n"
        :: "r"(addr), "r"(parity) : "memory");
}

// ---------------- kernel: double-buffered fp32 GEMM, 32-wide k-tiles ----------------
// C[M,N] = A[M,K] @ W[N,K]^T + bias
// mode 0: C row-major by A-row.
// mode 1: A-row=(t*B+b) remapped to out[(b*T+t)*N+n] (logits)
// mode 2: A-row gathered through embedding: A[m][k] = emb[x[b*T+t]][k]  (K=Esz)
// vs R12: k-tile widened 16->32 (halves __syncthreads count + loop overhead, doubles
// prefetch distance). One sync per 32-k tile; LDG(next) in flight during compute(cur).
__global__ void __launch_bounds__(256,2) k_gemm(const float* __restrict__ A,
                                                const float* __restrict__ W,
                                                const float* __restrict__ bias,
                                                float* __restrict__ C,
                                                int M, int N, int K, int mode,
                                                const int* __restrict__ xidx){
    __shared__ __align__(16) float As[2][128*36];   // [m][k], k=32 + pad4 (stride 36)
    __shared__ __align__(16) float Bs[2][32*130];   // [k][n], row stride 130 (pad)
    const int tid = threadIdx.x;
    const int m0 = blockIdx.x*128;
    const int n0 = blockIdx.y*128;
    const int tx = tid & 15;       // n-group (8 n each)
    const int ty = tid >> 4;       // m-group (8 m each)
    const int mlA = tid >> 2, qA = tid & 3;
    const int nnB = tid & 127, hfB = tid >> 7;
    const int nt = K >> 5;         // 32-wide tiles

    // hoisted A/B base pointers (gather index resolved ONCE, not per tile)
    const float* aptr[2];
#pragma unroll
    for (int p=0;p<2;p++){
        int row = m0 + mlA + p*64;
        if (mode == 2){
            int b = row & 63; int tt = row >> 6;
            int v = xidx[b*Tsz + tt];
            aptr[p] = &A[(size_t)v*Esz + qA*4];
        } else {
            aptr[p] = &A[(size_t)row*K + qA*4];
        }
    }
    const float* bptr = &W[(size_t)(n0+nnB)*K + hfB*8];

    ull acc[8][4];
#pragma unroll
    for (int i=0;i<8;i++)
#pragma unroll
        for (int j=0;j<4;j++) acc[i][j] = 0ull;

    float4 ra0, ra1, ra2, ra3, rb0, rb1, rb2, rb3;
    auto stage = [&](int buf){
        *(float4*)&As[buf][(mlA     )*36 + qA*4     ] = ra0;
        *(float4*)&As[buf][(mlA + 64)*36 + qA*4     ] = ra1;
        *(float4*)&As[buf][(mlA     )*36 + qA*4 + 16] = ra2;
        *(float4*)&As[buf][(mlA + 64)*36 + qA*4 + 16] = ra3;
        int kb = hfB*8;
        Bs[buf][(kb+0)*130+nnB]=rb0.x; Bs[buf][(kb+1)*130+nnB]=rb0.y;
        Bs[buf][(kb+2)*130+nnB]=rb0.z; Bs[buf][(kb+3)*130+nnB]=rb0.w;
        Bs[buf][(kb+4)*130+nnB]=rb1.x; Bs[buf][(kb+5)*130+nnB]=rb1.y;
        Bs[buf][(kb+6)*130+nnB]=rb1.z; Bs[buf][(kb+7)*130+nnB]=rb1.w;
        int kb2 = kb + 16;
        Bs[buf][(kb2+0)*130+nnB]=rb2.x; Bs[buf][(kb2+1)*130+nnB]=rb2.y;
        Bs[buf][(kb2+2)*130+nnB]=rb2.z; Bs[buf][(kb2+3)*130+nnB]=rb2.w;
        Bs[buf][(kb2+4)*130+nnB]=rb3.x; Bs[buf][(kb2+5)*130+nnB]=rb3.y;
        Bs[buf][(kb2+6)*130+nnB]=rb3.z; Bs[buf][(kb2+7)*130+nnB]=rb3.w;
    };
    auto loadtile = [&](int k0){
        ra0 = *(const float4*)(aptr[0] + k0);
        ra1 = *(const float4*)(aptr[1] + k0);
        ra2 = *(const float4*)(aptr[0] + k0 + 16);
        ra3 = *(const float4*)(aptr[1] + k0 + 16);
        rb0 = *(const float4*)(bptr + k0);
        rb1 = *(const float4*)(bptr + k0 + 4);
        rb2 = *(const float4*)(bptr + k0 + 16);
        rb3 = *(const float4*)(bptr + k0 + 20);
    };

    // ---- prologue: stage tile 0 ----
    loadtile(0);
    stage(0);
    __syncthreads();

    for (int kt=0; kt<nt; kt++){
        const int cur = kt & 1;
        const bool more = (kt+1 < nt);
        if (more) loadtile((kt+1) << 5);
        // compute on buffer cur (LDG for next tile in flight)
        const float* Asc = As[cur];
        const float* Bsc = Bs[cur];
#pragma unroll
        for (int half=0; half<2; half++){
#pragma unroll
            for (int kk=0;kk<16;kk++){
                int k = half*16 + ((kk + tx) & 15);    // per-lane k rotation: no conflicts
                const ull* bp = (const ull*)&Bsc[k*130 + tx*8];
                ull b0=bp[0], b1=bp[1], b2v=bp[2], b3=bp[3];
#pragma unroll
                for (int i=0;i<8;i++){
                    ull a2 = pack2(Asc[(ty*8+i)*36 + k]);
                    acc[i][0] = fma2(a2, b0,  acc[i][0]);
                    acc[i][1] = fma2(a2, b1,  acc[i][1]);
                    acc[i][2] = fma2(a2, b2v, acc[i][2]);
                    acc[i][3] = fma2(a2, b3,  acc[i][3]);
                }
            }
        }
        if (more){
            stage(cur ^ 1);
            __syncthreads();
        }
    }
    // epilogue: + bias, write (with optional logits remap)
#pragma unroll
    for (int i=0;i<8;i++){
        int row = m0 + ty*8 + i;
        size_t obase;
        if (mode == 1){ int b = row & 63; int tt = row >> 6; obase = ((size_t)b*Tsz + tt)*(size_t)N; }
        else obase = (size_t)row * (size_t)N;
#pragma unroll
        for (int jn=0;jn<4;jn++){
            int n = n0 + tx*8 + jn*2;
            float2 bv = *(const float2*)&bias[n];
            float lo, hi; unpack2(acc[i][jn], lo, hi);
            float2 o; o.x = lo + bv.x; o.y = hi + bv.y;
            *(float2*)&C[obase + n] = o;
        }
    }
}

// ---------------- kernel: two-stream st.async recurrence (R10/R12 champion) ----------
// 128 CTAs = 16 clusters x 8 CTAs, 256 thr. Cluster cl owns batches [cl*4, cl*4+4):
// stream A = {+0,+1}, stream B = {+2,+3} (independent chains, SAME weight regs).
// Sync: per-(stream,slot) tx-counting mbarrier; st.async self-signaling pushes; no
// fences, no cluster barrier in the loop. Changes vs R12 (critical-path reorder only):
//   - next-step xw prefetch issued right after each stream's wait (LDG flies under FMA)
//   - push_async issued BEFORE the hs global store (consumers wait on the push)
#define CH   36                    // 32 floats + 4 pad per k-slice
#define HB   (2*16*CH)             // 2 batches x 16 slices = 1152 floats per region
#define HB4  (HB*4)                // bytes per region
#define TXB  4096u                 // inbound bytes per mbar phase: 1024 floats

__global__ void __launch_bounds__(256,1) __cluster_dims__(8,1,1)
k_rnn(const float* __restrict__ xw, float* __restrict__ hs,
      const float* __restrict__ Whh, float* __restrict__ hlast){
    __shared__ __align__(16) float sh[4*HB];             // region = stream*2 + slot
    __shared__ __align__(8) ull mb[4];                   // mbar per region
    const int cl   = blockIdx.x >> 3;
    const int rank = blockIdx.x & 7;
    const int tid  = threadIdx.x;
    const int w    = tid >> 5;
    const int lane = tid & 31;
    const int jq   = lane >> 4;
    const int kq   = lane & 15;
    const int j0   = rank*64 + w*8 + jq*4;
    const int bw   = (kq >> 3) & 1;          // batch within stream
    const int j_out= j0 + ((kq >> 1) & 3);
    const int odd  = kq & 1;
    const int bA   = cl*4 + bw;              // absolute batch, stream A output
    const int bB   = cl*4 + 2 + bw;          // absolute batch, stream B output
    const int BH   = Bsz*Hsz;

    // ---- weights: W_hh[j0+jj][kq*32 .. +32) as 16 f32x2 each (serve both streams) ----
    ull w2[4][16];
#pragma unroll
    for (int jj=0;jj<4;jj++){
        const ull* wp = (const ull*)(Whh + (size_t)(j0+jj)*Hsz + kq*32);
#pragma unroll
        for (int i=0;i<16;i++) w2[jj][i] = wp[i];
    }

    // ---- mbar init, cluster-wide visibility, then arm phase 0 of all 4 ----
    const unsigned mb_base = smem_u32(mb);
    if (tid == 0){
#pragma unroll
        for (int i=0;i<4;i++) mbar_init(mb_base + i*8, 1u);
    }
    __syncthreads();
    cluster_arrive(); cluster_wait();        // inits visible before any inbound st.async
    if (tid == 0){
#pragma unroll
        for (int i=0;i<4;i++) mbar_expect(mb_base + i*8, TXB);
    }

    // ---- DSMEM push addresses (data + mbar, SAME 4 ranks) ----
    const unsigned sbase = smem_u32(sh);
    unsigned rsh[4], rmb[4];
#pragma unroll
    for (int r=0;r<4;r++){
        rsh[r] = mapa_rank(sbase,   odd*4 + r);
        rmb[r] = mapa_rank(mb_base, odd*4 + r);
    }
    // consumer layout within a region: ((b*16 + (k>>5))*CH + (k&31)); our k = j_out
    const unsigned inner = (unsigned)(((bw*16 + (j_out>>5))*CH + (j_out&31))*4);

    const float* xwpA = xw + (size_t)bA*Hsz + j_out;
    const float* xwpB = xw + (size_t)bB*Hsz + j_out;
    float*       hspA = hs + (size_t)bA*Hsz + j_out;
    float*       hspB = hs + (size_t)bB*Hsz + j_out;

    const bool hi8 = (lane & 8) != 0;
    const bool hi4 = (lane & 4) != 0;
    const bool hi2 = (lane & 2) != 0;

    // per-stream FMA+reduce over region bi (verified in R7/R10)
    auto stream_mv = [&](int bi)->float{
        const float* buf = sh + bi*HB;
        ull acc[2][4];
#pragma unroll
        for (int b=0;b<2;b++)
#pragma unroll
            for (int jj=0;jj<4;jj++) acc[b][jj] = 0ull;
#pragma unroll
        for (int b=0;b<2;b++){
            const ull* hq = (const ull*)(buf + (b*16 + kq)*CH);
#pragma unroll
            for (int kk=0;kk<16;kk+=2){
                ulonglong2 p = *(const ulonglong2*)&hq[kk];
#pragma unroll
                for (int jj=0;jj<4;jj++){
                    acc[b][jj] = fma2(p.x, w2[jj][kk],   acc[b][jj]);
                    acc[b][jj] = fma2(p.y, w2[jj][kk+1], acc[b][jj]);
                }
            }
        }
        float v[8];
#pragma unroll
        for (int b=0;b<2;b++)
#pragma unroll
            for (int jj=0;jj<4;jj++){
                float l, h; unpack2(acc[b][jj], l, h);
                v[b*4+jj] = l + h;
            }
#pragma unroll
        for (int o=0;o<4;o++){
            float keepv = hi8 ? v[o+4] : v[o];
            float sendv = hi8 ? v[o]   : v[o+4];
            v[o] = keepv + __shfl_xor_sync(0xffffffffu, sendv, 8);
        }
#pragma unroll
        for (int o=0;o<2;o++){
            float keepv = hi4 ? v[o+2] : v[o];
            float sendv = hi4 ? v[o]   : v[o+2];
            v[o] = keepv + __shfl_xor_sync(0xffffffffu, sendv, 4);
        }
        {
            float keepv = hi2 ? v[1] : v[0];
            float sendv = hi2 ? v[0] : v[1];
            v[0] = keepv + __shfl_xor_sync(0xffffffffu, sendv, 2);
        }
        v[0] += __shfl_xor_sync(0xffffffffu, v[0], 1);
        return v[0];
    };

    // push one output to 4 ranks, each store self-signals that rank's region mbar
    auto push_async = [&](float hv, int region){
        unsigned woff = (unsigned)(region*HB4) + inner;
        unsigned moff = (unsigned)(region*8);
#pragma unroll
        for (int r=0;r<4;r++) st_async(rsh[r] + woff, hv, rmb[r] + moff);
    };

    // ---- t = 0 (h_prev = 0) ----
    float xwA = xwpA[0], xwB = xwpB[0];
    {
        float hvA = ftanh(xwA);
        push_async(hvA, 0);                  // stream A, slot 0
        if (!odd) hspA[0] = hvA;
        float hvB = ftanh(xwB);
        push_async(hvB, 2);                  // stream B, slot 0
        if (odd) hspB[0] = hvB;
    }
    xwA = xwpA[BH];  xwB = xwpB[BH];         // prefetch t=1

    for (int t=1;t<Tsz;t++){
        const int m   = (t-1) & 1;                       // mbar/buffer slot of h[t-1]
        const unsigned par = (unsigned)(((t-1) >> 1) & 1);
        const int slot = t & 1;                          // slot for h[t]
        const int toff = t << 15;                        // t*BH

        // ---------- stream A ----------
        mbar_wait(mb_base + (0*2+m)*8, par);             // h[t-1] of A complete
        if (tid == 0 && t <= 509) mbar_expect(mb_base + (0*2+m)*8, TXB);  // arm h[t+1]
        float xwA_n = 0.f;
        if (t != Tsz-1) xwA_n = xwpA[toff + BH];         // prefetch: LDG flies under FMA
        float sumA = stream_mv(0*2 + m);
        float hvA = ftanh(sumA + xwA);
        if (t <= 510) push_async(hvA, 0*2 + slot);       // push FIRST (critical path)
        if (!odd) hspA[toff] = hvA;
        if (t != Tsz-1) xwA = xwA_n;
        else if (!odd)  hlast[bA*Hsz + j_out] = hvA;

        // ---------- stream B ----------
        mbar_wait(mb_base + (1*2+m)*8, par);             // h[t-1] of B complete
        if (tid == 0 && t <= 509) mbar_expect(mb_base + (1*2+m)*8, TXB);
        float xwB_n = 0.f;
        if (t != Tsz-1) xwB_n = xwpB[toff + BH];
        float sumB = stream_mv(1*2 + m);
        float hvB = ftanh(sumB + xwB);
        if (t <= 510) push_async(hvB, 1*2 + slot);
        if (odd) hspB[toff] = hvB;
        if (t != Tsz-1) xwB = xwB_n;
        else if (odd)   hlast[bB*Hsz + j_out] = hvB;
    }
    // no drain needed: t=511 pushed nothing; final waits consumed all inbound tx
}

// ---------------- launch -------------------------------------------------------------
extern "C" void kernel_launch(void* const* d_in, const int* in_sizes, int n_in,
                              void* d_out, int out_size){
    const int*   x    = (const int*)  d_in[0];
    const float* emb  = (const float*)d_in[1];
    const float* Wxh0 = (const float*)d_in[2];
    const float* Whh0 = (const float*)d_in[3];
    const float* bh0  = (const float*)d_in[4];
    const float* Wxh1 = (const float*)d_in[5];
    const float* Whh1 = (const float*)d_in[6];
    const float* bh1  = (const float*)d_in[7];
    const float* Why  = (const float*)d_in[8];
    const float* by   = (const float*)d_in[9];
    float* out = (float*)d_out;

    float *xwbuf, *hs0, *hs1;
    cudaGetSymbolAddress((void**)&xwbuf, g_xw);
    cudaGetSymbolAddress((void**)&hs0,   g_hs0);
    cudaGetSymbolAddress((void**)&hs1,   g_hs1);

    const size_t LOGITS = (size_t)Bsz*Tsz*Vsz;   // 4194304

    dim3 gH(Msz/128, Hsz/128);

    // 1) xw0 = gather(emb, x) @ Wxh0^T + bh0   (gather fused into A-load)
    k_gemm<<<gH, 256>>>(emb, Wxh0, bh0, xwbuf, Msz, Hsz, Esz, 2, x);

    // 2) layer-0 recurrence -> hs0, h_last0
    k_rnn<<<128, 256>>>(xwbuf, hs0, Whh0, out + LOGITS);

    // 3) xw1 = hs0 @ Wxh1^T + bh1
    k_gemm<<<gH, 256>>>(hs0, Wxh1, bh1, xwbuf, Msz, Hsz, Hsz, 0, 0);

    // 4) layer-1 recurrence -> hs1, h_last1
    k_rnn<<<128, 256>>>(xwbuf, hs1, Whh1, out + LOGITS + (size_t)Bsz*Hsz);

    // 5) logits = hs1 @ Why^T + by  (remapped to (b,t,v))
    dim3 gV(Msz/128, Vsz/128);
    k_gemm<<<gV, 256>>>(hs1, Why, by, out, Msz, Vsz, Hsz, 1, 0);
}

// round 16
// speedup vs baseline: 1.0622x; 1.0318x over previous
#include <cuda_runtime.h>
#include <math.h>

typedef unsigned long long ull;

#define Bsz 64
#define Tsz 512
#define Esz 256
#define Hsz 512
#define Vsz 128
#define Msz (Bsz*Tsz)   // 32768 rows

// ---------------- scratch (static device arrays; no runtime allocation) -------------
__device__ float g_xw[Msz*Hsz];     // input projection for current layer (t,b,h)
__device__ float g_hs0[Msz*Hsz];    // layer0 hidden states (t,b,h)
__device__ float g_hs1[Msz*Hsz];    // layer1 hidden states (t,b,h)

// ---------------- f32x2 helpers ------------------------------------------------------
__device__ __forceinline__ ull fma2(ull a, ull b, ull c){
    ull d; asm("fma.rn.f32x2 %0, %1, %2, %3;" : "=l"(d) : "l"(a), "l"(b), "l"(c)); return d;
}
__device__ __forceinline__ ull pack2(float x){
    ull d; asm("mov.b64 %0, {%1, %1};" : "=l"(d) : "f"(x)); return d;
}
__device__ __forceinline__ void unpack2(ull v, float& lo, float& hi){
    asm("mov.b64 {%0, %1}, %2;" : "=f"(lo), "=f"(hi) : "l"(v));
}

// branch-free tanh: 1 - 2/(e^{2x}+1). MUFU-based, ~5 instr, rel err ~3e-7.
__device__ __forceinline__ float ftanh(float x){
    float e = __expf(2.0f*x);
    return 1.0f - __fdividef(2.0f, e + 1.0f);
}

// ---------------- cluster helpers ----------------------------------------------------
__device__ __forceinline__ unsigned smem_u32(const void* p){
    unsigned a;
    asm("{ .reg .u64 t; cvta.to.shared.u64 t, %1; cvt.u32.u64 %0, t; }" : "=r"(a) : "l"(p));
    return a;
}
__device__ __forceinline__ unsigned mapa_rank(unsigned laddr, unsigned r){
    unsigned ra; asm("mapa.shared::cluster.u32 %0, %1, %2;" : "=r"(ra) : "r"(laddr), "r"(r));
    return ra;
}
__device__ __forceinline__ void cluster_arrive(){
    asm volatile("barrier.cluster.arrive.aligned;" ::: "memory");
}
__device__ __forceinline__ void cluster_wait(){
    asm volatile("barrier.cluster.wait.aligned;"   ::: "memory");
}
__device__ __forceinline__ void mbar_init(unsigned addr, unsigned cnt){
    asm volatile("mbarrier.init.shared.b64 [%0], %1;" :: "r"(addr), "r"(cnt) : "memory");
}
// arm: arrive (count 1) + expect tx bytes for the current phase of own mbar
__device__ __forceinline__ void mbar_expect(unsigned addr, unsigned txb){
    asm volatile("mbarrier.arrive.expect_tx.shared.b64 _, [%0], %1;"
                 :: "r"(addr), "r"(txb) : "memory");
}
// self-signaling remote store: data + tx-completion both to the SAME remote CTA
__device__ __forceinline__ void st_async(unsigned raddr, float v, unsigned rmbar){
    asm volatile("st.async.shared::cluster.mbarrier::complete_tx::bytes.u32 [%0], %1, [%2];"
                 :: "r"(raddr), "r"(__float_as_uint(v)), "r"(rmbar) : "memory");
}
// wait own mbar phase with cluster-scope acquire (orders inbound async stores)
__device__ __forceinline__ void mbar_wait(unsigned addr, unsigned parity){
    asm volatile("{\n\t.reg .pred P;\n\t"
        "W_%=:\n\t"
        "mbarrier.try_wait.parity.acquire.cluster.shared::cta.b64 P, [%0], %1, 0x989680;\n\t"
        "@!P bra W_%=;\n\t}\n"
        :: "r"(addr), "r"(parity) : "memory");
}

// ---------------- kernel: double-buffered fp32 GEMM, k-major A tile -----------------
// C[M,N] = A[M,K] @ W[N,K]^T + bias
// mode 0: C row-major by A-row.
// mode 1: A-row=(t*B+b) remapped to out[(b*T+t)*N+n] (logits)
// mode 2: A-row gathered through embedding: A[m][k] = emb[x[b*T+t]][k]  (K=Esz)
// vs R15: As stored K-MAJOR (As[k][m], stride 132). Compute reads A as 2x LDS.128
// with only 2 distinct addresses/warp (ty-broadcast, ~1 phase) instead of 8 scalar
// LDS.32 with 2-way conflicts; per-i duplication moves to pack2 MOVs on the idle ALU
// pipe. Crossbar phases/warp/k: ~24 -> ~6; LSU drops below the FMA floor.
__global__ void __launch_bounds__(256,2) k_gemm(const float* __restrict__ A,
                                                const float* __restrict__ W,
                                                const float* __restrict__ bias,
                                                float* __restrict__ C,
                                                int M, int N, int K, int mode,
                                                const int* __restrict__ xidx){
    __shared__ __align__(16) float As[2][32*132];   // [k][m], 128 m + 4 pad
    __shared__ __align__(16) float Bs[2][32*130];   // [k][n], row stride 130 (pad)
    const int tid = threadIdx.x;
    const int m0 = blockIdx.x*128;
    const int n0 = blockIdx.y*128;
    const int tx = tid & 15;       // n-group (8 n each)
    const int ty = tid >> 4;       // m-group (8 m each)
    const int mlA = tid >> 2, qA = tid & 3;
    const int nnB = tid & 127, hfB = tid >> 7;
    const int nt = K >> 5;         // 32-wide tiles

    // hoisted A/B base pointers (gather index resolved ONCE, not per tile)
    const float* aptr[2];
#pragma unroll
    for (int p=0;p<2;p++){
        int row = m0 + mlA + p*64;
        if (mode == 2){
            int b = row & 63; int tt = row >> 6;
            int v = xidx[b*Tsz + tt];
            aptr[p] = &A[(size_t)v*Esz + qA*4];
        } else {
            aptr[p] = &A[(size_t)row*K + qA*4];
        }
    }
    const float* bptr = &W[(size_t)(n0+nnB)*K + hfB*8];

    ull acc[8][4];
#pragma unroll
    for (int i=0;i<8;i++)
#pragma unroll
        for (int j=0;j<4;j++) acc[i][j] = 0ull;

    float4 ra0, ra1, ra2, ra3, rb0, rb1, rb2, rb3;
    auto stage = [&](int buf){
        // A k-major: rows k = qA*4+j (and +16), columns m = mlA / mlA+64
        const float* a0 = &ra0.x; const float* a1 = &ra1.x;
        const float* a2p= &ra2.x; const float* a3p= &ra3.x;
#pragma unroll
        for (int j=0;j<4;j++){
            As[buf][(qA*4+j   )*132 + mlA     ] = a0[j];
            As[buf][(qA*4+j   )*132 + mlA + 64] = a1[j];
            As[buf][(qA*4+j+16)*132 + mlA     ] = a2p[j];
            As[buf][(qA*4+j+16)*132 + mlA + 64] = a3p[j];
        }
        int kb = hfB*8;
        Bs[buf][(kb+0)*130+nnB]=rb0.x; Bs[buf][(kb+1)*130+nnB]=rb0.y;
        Bs[buf][(kb+2)*130+nnB]=rb0.z; Bs[buf][(kb+3)*130+nnB]=rb0.w;
        Bs[buf][(kb+4)*130+nnB]=rb1.x; Bs[buf][(kb+5)*130+nnB]=rb1.y;
        Bs[buf][(kb+6)*130+nnB]=rb1.z; Bs[buf][(kb+7)*130+nnB]=rb1.w;
        int kb2 = kb + 16;
        Bs[buf][(kb2+0)*130+nnB]=rb2.x; Bs[buf][(kb2+1)*130+nnB]=rb2.y;
        Bs[buf][(kb2+2)*130+nnB]=rb2.z; Bs[buf][(kb2+3)*130+nnB]=rb2.w;
        Bs[buf][(kb2+4)*130+nnB]=rb3.x; Bs[buf][(kb2+5)*130+nnB]=rb3.y;
        Bs[buf][(kb2+6)*130+nnB]=rb3.z; Bs[buf][(kb2+7)*130+nnB]=rb3.w;
    };
    auto loadtile = [&](int k0){
        ra0 = *(const float4*)(aptr[0] + k0);
        ra1 = *(const float4*)(aptr[1] + k0);
        ra2 = *(const float4*)(aptr[0] + k0 + 16);
        ra3 = *(const float4*)(aptr[1] + k0 + 16);
        rb0 = *(const float4*)(bptr + k0);
        rb1 = *(const float4*)(bptr + k0 + 4);
        rb2 = *(const float4*)(bptr + k0 + 16);
        rb3 = *(const float4*)(bptr + k0 + 20);
    };

    // ---- prologue: stage tile 0 ----
    loadtile(0);
    stage(0);
    __syncthreads();

    for (int kt=0; kt<nt; kt++){
        const int cur = kt & 1;
        const bool more = (kt+1 < nt);
        if (more) loadtile((kt+1) << 5);
        // compute on buffer cur (LDG for next tile in flight)
        const float* Asc = As[cur];
        const float* Bsc = Bs[cur];
#pragma unroll 1
        for (int kh=0; kh<2; kh++){
#pragma unroll
            for (int kk=0;kk<16;kk++){
                const int k = kh*16 + kk;
                const ull* bp = (const ull*)&Bsc[k*130 + tx*8];
                ull b0=bp[0], b1=bp[1], b2v=bp[2], b3=bp[3];
                // A row k: 8 consecutive m-values via 2 broadcast LDS.128
                float4 av0 = *(const float4*)&Asc[k*132 + ty*8];
                float4 av1 = *(const float4*)&Asc[k*132 + ty*8 + 4];
                ull a2[8];
                a2[0]=pack2(av0.x); a2[1]=pack2(av0.y); a2[2]=pack2(av0.z); a2[3]=pack2(av0.w);
                a2[4]=pack2(av1.x); a2[5]=pack2(av1.y); a2[6]=pack2(av1.z); a2[7]=pack2(av1.w);
#pragma unroll
                for (int i=0;i<8;i++){
                    acc[i][0] = fma2(a2[i], b0,  acc[i][0]);
                    acc[i][1] = fma2(a2[i], b1,  acc[i][1]);
                    acc[i][2] = fma2(a2[i], b2v, acc[i][2]);
                    acc[i][3] = fma2(a2[i], b3,  acc[i][3]);
                }
            }
        }
        if (more){
            stage(cur ^ 1);
            __syncthreads();
        }
    }
    // epilogue: + bias, write (with optional logits remap)
#pragma unroll
    for (int i=0;i<8;i++){
        int row = m0 + ty*8 + i;
        size_t obase;
        if (mode == 1){ int b = row & 63; int tt = row >> 6; obase = ((size_t)b*Tsz + tt)*(size_t)N; }
        else obase = (size_t)row * (size_t)N;
#pragma unroll
        for (int jn=0;jn<4;jn++){
            int n = n0 + tx*8 + jn*2;
            float2 bv = *(const float2*)&bias[n];
            float lo, hi; unpack2(acc[i][jn], lo, hi);
            float2 o; o.x = lo + bv.x; o.y = hi + bv.y;
            *(float2*)&C[obase + n] = o;
        }
    }
}

// ---------------- kernel: two-stream st.async recurrence (R15 champion, verbatim) ----
// 128 CTAs = 16 clusters x 8 CTAs, 256 thr. Cluster cl owns batches [cl*4, cl*4+4):
// stream A = {+0,+1}, stream B = {+2,+3} (independent chains, SAME weight regs).
// Sync: per-(stream,slot) tx-counting mbarrier; st.async self-signaling pushes; no
// fences, no cluster barrier in the loop. xw prefetch right after each wait; push
// before the hs global store (consumers wait on the push, not the STG).
#define CH   36                    // 32 floats + 4 pad per k-slice
#define HB   (2*16*CH)             // 2 batches x 16 slices = 1152 floats per region
#define HB4  (HB*4)                // bytes per region
#define TXB  4096u                 // inbound bytes per mbar phase: 1024 floats

__global__ void __launch_bounds__(256,1) __cluster_dims__(8,1,1)
k_rnn(const float* __restrict__ xw, float* __restrict__ hs,
      const float* __restrict__ Whh, float* __restrict__ hlast){
    __shared__ __align__(16) float sh[4*HB];             // region = stream*2 + slot
    __shared__ __align__(8) ull mb[4];                   // mbar per region
    const int cl   = blockIdx.x >> 3;
    const int rank = blockIdx.x & 7;
    const int tid  = threadIdx.x;
    const int w    = tid >> 5;
    const int lane = tid & 31;
    const int jq   = lane >> 4;
    const int kq   = lane & 15;
    const int j0   = rank*64 + w*8 + jq*4;
    const int bw   = (kq >> 3) & 1;          // batch within stream
    const int j_out= j0 + ((kq >> 1) & 3);
    const int odd  = kq & 1;
    const int bA   = cl*4 + bw;              // absolute batch, stream A output
    const int bB   = cl*4 + 2 + bw;          // absolute batch, stream B output
    const int BH   = Bsz*Hsz;

    // ---- weights: W_hh[j0+jj][kq*32 .. +32) as 16 f32x2 each (serve both streams) ----
    ull w2[4][16];
#pragma unroll
    for (int jj=0;jj<4;jj++){
        const ull* wp = (const ull*)(Whh + (size_t)(j0+jj)*Hsz + kq*32);
#pragma unroll
        for (int i=0;i<16;i++) w2[jj][i] = wp[i];
    }

    // ---- mbar init, cluster-wide visibility, then arm phase 0 of all 4 ----
    const unsigned mb_base = smem_u32(mb);
    if (tid == 0){
#pragma unroll
        for (int i=0;i<4;i++) mbar_init(mb_base + i*8, 1u);
    }
    __syncthreads();
    cluster_arrive(); cluster_wait();        // inits visible before any inbound st.async
    if (tid == 0){
#pragma unroll
        for (int i=0;i<4;i++) mbar_expect(mb_base + i*8, TXB);
    }

    // ---- DSMEM push addresses (data + mbar, SAME 4 ranks) ----
    const unsigned sbase = smem_u32(sh);
    unsigned rsh[4], rmb[4];
#pragma unroll
    for (int r=0;r<4;r++){
        rsh[r] = mapa_rank(sbase,   odd*4 + r);
        rmb[r] = mapa_rank(mb_base, odd*4 + r);
    }
    // consumer layout within a region: ((b*16 + (k>>5))*CH + (k&31)); our k = j_out
    const unsigned inner = (unsigned)(((bw*16 + (j_out>>5))*CH + (j_out&31))*4);

    const float* xwpA = xw + (size_t)bA*Hsz + j_out;
    const float* xwpB = xw + (size_t)bB*Hsz + j_out;
    float*       hspA = hs + (size_t)bA*Hsz + j_out;
    float*       hspB = hs + (size_t)bB*Hsz + j_out;

    const bool hi8 = (lane & 8) != 0;
    const bool hi4 = (lane & 4) != 0;
    const bool hi2 = (lane & 2) != 0;

    // per-stream FMA+reduce over region bi (verified in R7/R10)
    auto stream_mv = [&](int bi)->float{
        const float* buf = sh + bi*HB;
        ull acc[2][4];
#pragma unroll
        for (int b=0;b<2;b++)
#pragma unroll
            for (int jj=0;jj<4;jj++) acc[b][jj] = 0ull;
#pragma unroll
        for (int b=0;b<2;b++){
            const ull* hq = (const ull*)(buf + (b*16 + kq)*CH);
#pragma unroll
            for (int kk=0;kk<16;kk+=2){
                ulonglong2 p = *(const ulonglong2*)&hq[kk];
#pragma unroll
                for (int jj=0;jj<4;jj++){
                    acc[b][jj] = fma2(p.x, w2[jj][kk],   acc[b][jj]);
                    acc[b][jj] = fma2(p.y, w2[jj][kk+1], acc[b][jj]);
                }
            }
        }
        float v[8];
#pragma unroll
        for (int b=0;b<2;b++)
#pragma unroll
            for (int jj=0;jj<4;jj++){
                float l, h; unpack2(acc[b][jj], l, h);
                v[b*4+jj] = l + h;
            }
#pragma unroll
        for (int o=0;o<4;o++){
            float keepv = hi8 ? v[o+4] : v[o];
            float sendv = hi8 ? v[o]   : v[o+4];
            v[o] = keepv + __shfl_xor_sync(0xffffffffu, sendv, 8);
        }
#pragma unroll
        for (int o=0;o<2;o++){
            float keepv = hi4 ? v[o+2] : v[o];
            float sendv = hi4 ? v[o]   : v[o+2];
            v[o] = keepv + __shfl_xor_sync(0xffffffffu, sendv, 4);
        }
        {
            float keepv = hi2 ? v[1] : v[0];
            float sendv = hi2 ? v[0] : v[1];
            v[0] = keepv + __shfl_xor_sync(0xffffffffu, sendv, 2);
        }
        v[0] += __shfl_xor_sync(0xffffffffu, v[0], 1);
        return v[0];
    };

    // push one output to 4 ranks, each store self-signals that rank's region mbar
    auto push_async = [&](float hv, int region){
        unsigned woff = (unsigned)(region*HB4) + inner;
        unsigned moff = (unsigned)(region*8);
#pragma unroll
        for (int r=0;r<4;r++) st_async(rsh[r] + woff, hv, rmb[r] + moff);
    };

    // ---- t = 0 (h_prev = 0) ----
    float xwA = xwpA[0], xwB = xwpB[0];
    {
        float hvA = ftanh(xwA);
        push_async(hvA, 0);                  // stream A, slot 0
        if (!odd) hspA[0] = hvA;
        float hvB = ftanh(xwB);
        push_async(hvB, 2);                  // stream B, slot 0
        if (odd) hspB[0] = hvB;
    }
    xwA = xwpA[BH];  xwB = xwpB[BH];         // prefetch t=1

    for (int t=1;t<Tsz;t++){
        const int m   = (t-1) & 1;                       // mbar/buffer slot of h[t-1]
        const unsigned par = (unsigned)(((t-1) >> 1) & 1);
        const int slot = t & 1;                          // slot for h[t]
        const int toff = t << 15;                        // t*BH

        // ---------- stream A ----------
        mbar_wait(mb_base + (0*2+m)*8, par);             // h[t-1] of A complete
        if (tid == 0 && t <= 509) mbar_expect(mb_base + (0*2+m)*8, TXB);  // arm h[t+1]
        float xwA_n = 0.f;
        if (t != Tsz-1) xwA_n = xwpA[toff + BH];         // prefetch: LDG flies under FMA
        float sumA = stream_mv(0*2 + m);
        float hvA = ftanh(sumA + xwA);
        if (t <= 510) push_async(hvA, 0*2 + slot);       // push FIRST (critical path)
        if (!odd) hspA[toff] = hvA;
        if (t != Tsz-1) xwA = xwA_n;
        else if (!odd)  hlast[bA*Hsz + j_out] = hvA;

        // ---------- stream B ----------
        mbar_wait(mb_base + (1*2+m)*8, par);             // h[t-1] of B complete
        if (tid == 0 && t <= 509) mbar_expect(mb_base + (1*2+m)*8, TXB);
        float xwB_n = 0.f;
        if (t != Tsz-1) xwB_n = xwpB[toff + BH];
        float sumB = stream_mv(1*2 + m);
        float hvB = ftanh(sumB + xwB);
        if (t <= 510) push_async(hvB, 1*2 + slot);
        if (odd) hspB[toff] = hvB;
        if (t != Tsz-1) xwB = xwB_n;
        else if (odd)   hlast[bB*Hsz + j_out] = hvB;
    }
    // no drain needed: t=511 pushed nothing; final waits consumed all inbound tx
}

// ---------------- launch -------------------------------------------------------------
extern "C" void kernel_launch(void* const* d_in, const int* in_sizes, int n_in,
                              void* d_out, int out_size){
    const int*   x    = (const int*)  d_in[0];
    const float* emb  = (const float*)d_in[1];
    const float* Wxh0 = (const float*)d_in[2];
    const float* Whh0 = (const float*)d_in[3];
    const float* bh0  = (const float*)d_in[4];
    const float* Wxh1 = (const float*)d_in[5];
    const float* Whh1 = (const float*)d_in[6];
    const float* bh1  = (const float*)d_in[7];
    const float* Why  = (const float*)d_in[8];
    const float* by   = (const float*)d_in[9];
    float* out = (float*)d_out;

    float *xwbuf, *hs0, *hs1;
    cudaGetSymbolAddress((void**)&xwbuf, g_xw);
    cudaGetSymbolAddress((void**)&hs0,   g_hs0);
    cudaGetSymbolAddress((void**)&hs1,   g_hs1);

    const size_t LOGITS = (size_t)Bsz*Tsz*Vsz;   // 4194304

    dim3 gH(Msz/128, Hsz/128);

    // 1) xw0 = gather(emb, x) @ Wxh0^T + bh0   (gather fused into A-load)
    k_gemm<<<gH, 256>>>(emb, Wxh0, bh0, xwbuf, Msz, Hsz, Esz, 2, x);

    // 2) layer-0 recurrence -> hs0, h_last0
    k_rnn<<<128, 256>>>(xwbuf, hs0, Whh0, out + LOGITS);

    // 3) xw1 = hs0 @ Wxh1^T + bh1
    k_gemm<<<gH, 256>>>(hs0, Wxh1, bh1, xwbuf, Msz, Hsz, Hsz, 0, 0);

    // 4) layer-1 recurrence -> hs1, h_last1
    k_rnn<<<128, 256>>>(xwbuf, hs1, Whh1, out + LOGITS + (size_t)Bsz*Hsz);

    // 5) logits = hs1 @ Why^T + by  (remapped to (b,t,v))
    dim3 gV(Msz/128, Vsz/128);
    k_gemm<<<gV, 256>>>(hs1, Why, by, out, Msz, Vsz, Hsz, 1, 0);
}

// round 17
// speedup vs baseline: 1.0690x; 1.0064x over previous
#include <cuda_runtime.h>
#include <math.h>

typedef unsigned long long ull;

#define Bsz 64
#define Tsz 512
#define Esz 256
#define Hsz 512
#define Vsz 128
#define Msz (Bsz*Tsz)   // 32768 rows

// ---------------- scratch (static device arrays; no runtime allocation) -------------
__device__ float g_xw[Msz*Hsz];     // input projection for current layer (t,b,h)
__device__ float g_hs0[Msz*Hsz];    // layer0 hidden states (t,b,h)
__device__ float g_hs1[Msz*Hsz];    // layer1 hidden states (t,b,h)

// ---------------- f32x2 helpers ------------------------------------------------------
__device__ __forceinline__ ull fma2(ull a, ull b, ull c){
    ull d; asm("fma.rn.f32x2 %0, %1, %2, %3;" : "=l"(d) : "l"(a), "l"(b), "l"(c)); return d;
}
__device__ __forceinline__ ull pack2(float x){
    ull d; asm("mov.b64 %0, {%1, %1};" : "=l"(d) : "f"(x)); return d;
}
__device__ __forceinline__ void unpack2(ull v, float& lo, float& hi){
    asm("mov.b64 {%0, %1}, %2;" : "=f"(lo), "=f"(hi) : "l"(v));
}

// branch-free tanh: 1 - 2/(e^{2x}+1). MUFU-based, ~5 instr, rel err ~3e-7.
__device__ __forceinline__ float ftanh(float x){
    float e = __expf(2.0f*x);
    return 1.0f - __fdividef(2.0f, e + 1.0f);
}

// ---------------- cluster helpers ----------------------------------------------------
__device__ __forceinline__ unsigned smem_u32(const void* p){
    unsigned a;
    asm("{ .reg .u64 t; cvta.to.shared.u64 t, %1; cvt.u32.u64 %0, t; }" : "=r"(a) : "l"(p));
    return a;
}
__device__ __forceinline__ unsigned mapa_rank(unsigned laddr, unsigned r){
    unsigned ra; asm("mapa.shared::cluster.u32 %0, %1, %2;" : "=r"(ra) : "r"(laddr), "r"(r));
    return ra;
}
__device__ __forceinline__ void cluster_arrive(){
    asm volatile("barrier.cluster.arrive.aligned;" ::: "memory");
}
__device__ __forceinline__ void cluster_wait(){
    asm volatile("barrier.cluster.wait.aligned;"   ::: "memory");
}
__device__ __forceinline__ void mbar_init(unsigned addr, unsigned cnt){
    asm volatile("mbarrier.init.shared.b64 [%0], %1;" :: "r"(addr), "r"(cnt) : "memory");
}
// arm: arrive (count 1) + expect tx bytes for the current phase of own mbar
__device__ __forceinline__ void mbar_expect(unsigned addr, unsigned txb){
    asm volatile("mbarrier.arrive.expect_tx.shared.b64 _, [%0], %1;"
                 :: "r"(addr), "r"(txb) : "memory");
}
// self-signaling remote store: data + tx-completion both to the SAME remote CTA
__device__ __forceinline__ void st_async(unsigned raddr, float v, unsigned rmbar){
    asm volatile("st.async.shared::cluster.mbarrier::complete_tx::bytes.u32 [%0], %1, [%2];"
                 :: "r"(raddr), "r"(__float_as_uint(v)), "r"(rmbar) : "memory");
}
// wait own mbar phase with cluster-scope acquire (orders inbound async stores)
__device__ __forceinline__ void mbar_wait(unsigned addr, unsigned parity){
    asm volatile("{\n\t.reg .pred P;\n\t"
        "W_%=:\n\t"
        "mbarrier.try_wait.parity.acquire.cluster.shared::cta.b64 P, [%0], %1, 0x989680;\n\t"
        "@!P bra W_%=;\n\t}\n"
        :: "r"(addr), "r"(parity) : "memory");
}

// ---------------- kernel: double-buffered fp32 GEMM, k-major A tile -----------------
// C[M,N] = A[M,K] @ W[N,K]^T + bias
// mode 0: C row-major by A-row.
// mode 1: A-row=(t*B+b) remapped to out[(b*T+t)*N+n] (logits)
// mode 2: A-row gathered through embedding: A[m][k] = emb[x[b*T+t]][k]  (K=Esz)
// vs R16: compute body fully unrolled across the 32-k tile (ptxas pipelines LDS+pack2
// into FMA shadows); epilogue hoists bias loads and merges stores to 2x STG.128/row.
__global__ void __launch_bounds__(256,2) k_gemm(const float* __restrict__ A,
                                                const float* __restrict__ W,
                                                const float* __restrict__ bias,
                                                float* __restrict__ C,
                                                int M, int N, int K, int mode,
                                                const int* __restrict__ xidx){
    __shared__ __align__(16) float As[2][32*132];   // [k][m], 128 m + 4 pad
    __shared__ __align__(16) float Bs[2][32*130];   // [k][n], row stride 130 (pad)
    const int tid = threadIdx.x;
    const int m0 = blockIdx.x*128;
    const int n0 = blockIdx.y*128;
    const int tx = tid & 15;       // n-group (8 n each)
    const int ty = tid >> 4;       // m-group (8 m each)
    const int mlA = tid >> 2, qA = tid & 3;
    const int nnB = tid & 127, hfB = tid >> 7;
    const int nt = K >> 5;         // 32-wide tiles

    // hoisted A/B base pointers (gather index resolved ONCE, not per tile)
    const float* aptr[2];
#pragma unroll
    for (int p=0;p<2;p++){
        int row = m0 + mlA + p*64;
        if (mode == 2){
            int b = row & 63; int tt = row >> 6;
            int v = xidx[b*Tsz + tt];
            aptr[p] = &A[(size_t)v*Esz + qA*4];
        } else {
            aptr[p] = &A[(size_t)row*K + qA*4];
        }
    }
    const float* bptr = &W[(size_t)(n0+nnB)*K + hfB*8];

    ull acc[8][4];
#pragma unroll
    for (int i=0;i<8;i++)
#pragma unroll
        for (int j=0;j<4;j++) acc[i][j] = 0ull;

    float4 ra0, ra1, ra2, ra3, rb0, rb1, rb2, rb3;
    auto stage = [&](int buf){
        // A k-major: rows k = qA*4+j (and +16), columns m = mlA / mlA+64
        const float* a0 = &ra0.x; const float* a1 = &ra1.x;
        const float* a2p= &ra2.x; const float* a3p= &ra3.x;
#pragma unroll
        for (int j=0;j<4;j++){
            As[buf][(qA*4+j   )*132 + mlA     ] = a0[j];
            As[buf][(qA*4+j   )*132 + mlA + 64] = a1[j];
            As[buf][(qA*4+j+16)*132 + mlA     ] = a2p[j];
            As[buf][(qA*4+j+16)*132 + mlA + 64] = a3p[j];
        }
        int kb = hfB*8;
        Bs[buf][(kb+0)*130+nnB]=rb0.x; Bs[buf][(kb+1)*130+nnB]=rb0.y;
        Bs[buf][(kb+2)*130+nnB]=rb0.z; Bs[buf][(kb+3)*130+nnB]=rb0.w;
        Bs[buf][(kb+4)*130+nnB]=rb1.x; Bs[buf][(kb+5)*130+nnB]=rb1.y;
        Bs[buf][(kb+6)*130+nnB]=rb1.z; Bs[buf][(kb+7)*130+nnB]=rb1.w;
        int kb2 = kb + 16;
        Bs[buf][(kb2+0)*130+nnB]=rb2.x; Bs[buf][(kb2+1)*130+nnB]=rb2.y;
        Bs[buf][(kb2+2)*130+nnB]=rb2.z; Bs[buf][(kb2+3)*130+nnB]=rb2.w;
        Bs[buf][(kb2+4)*130+nnB]=rb3.x; Bs[buf][(kb2+5)*130+nnB]=rb3.y;
        Bs[buf][(kb2+6)*130+nnB]=rb3.z; Bs[buf][(kb2+7)*130+nnB]=rb3.w;
    };
    auto loadtile = [&](int k0){
        ra0 = *(const float4*)(aptr[0] + k0);
        ra1 = *(const float4*)(aptr[1] + k0);
        ra2 = *(const float4*)(aptr[0] + k0 + 16);
        ra3 = *(const float4*)(aptr[1] + k0 + 16);
        rb0 = *(const float4*)(bptr + k0);
        rb1 = *(const float4*)(bptr + k0 + 4);
        rb2 = *(const float4*)(bptr + k0 + 16);
        rb3 = *(const float4*)(bptr + k0 + 20);
    };

    // ---- prologue: stage tile 0 ----
    loadtile(0);
    stage(0);
    __syncthreads();

    for (int kt=0; kt<nt; kt++){
        const int cur = kt & 1;
        const bool more = (kt+1 < nt);
        if (more) loadtile((kt+1) << 5);
        // compute on buffer cur (LDG for next tile in flight); fully unrolled 32-k body
        const float* Asc = As[cur];
        const float* Bsc = Bs[cur];
#pragma unroll
        for (int k=0;k<32;k++){
            const ull* bp = (const ull*)&Bsc[k*130 + tx*8];
            ull b0=bp[0], b1=bp[1], b2v=bp[2], b3=bp[3];
            // A row k: 8 consecutive m-values via 2 broadcast LDS.128
            float4 av0 = *(const float4*)&Asc[k*132 + ty*8];
            float4 av1 = *(const float4*)&Asc[k*132 + ty*8 + 4];
            ull a2[8];
            a2[0]=pack2(av0.x); a2[1]=pack2(av0.y); a2[2]=pack2(av0.z); a2[3]=pack2(av0.w);
            a2[4]=pack2(av1.x); a2[5]=pack2(av1.y); a2[6]=pack2(av1.z); a2[7]=pack2(av1.w);
#pragma unroll
            for (int i=0;i<8;i++){
                acc[i][0] = fma2(a2[i], b0,  acc[i][0]);
                acc[i][1] = fma2(a2[i], b1,  acc[i][1]);
                acc[i][2] = fma2(a2[i], b2v, acc[i][2]);
                acc[i][3] = fma2(a2[i], b3,  acc[i][3]);
            }
        }
        if (more){
            stage(cur ^ 1);
            __syncthreads();
        }
    }
    // epilogue: + bias (hoisted), 2x STG.128 per row (outputs n = n0+tx*8 .. +7 contiguous)
    const float4 bv0 = *(const float4*)&bias[n0 + tx*8];
    const float4 bv1 = *(const float4*)&bias[n0 + tx*8 + 4];
#pragma unroll
    for (int i=0;i<8;i++){
        int row = m0 + ty*8 + i;
        size_t obase;
        if (mode == 1){ int b = row & 63; int tt = row >> 6; obase = ((size_t)b*Tsz + tt)*(size_t)N; }
        else obase = (size_t)row * (size_t)N;
        float4 o0, o1;
        { float lo, hi;
          unpack2(acc[i][0], lo, hi); o0.x = lo + bv0.x; o0.y = hi + bv0.y;
          unpack2(acc[i][1], lo, hi); o0.z = lo + bv0.z; o0.w = hi + bv0.w;
          unpack2(acc[i][2], lo, hi); o1.x = lo + bv1.x; o1.y = hi + bv1.y;
          unpack2(acc[i][3], lo, hi); o1.z = lo + bv1.z; o1.w = hi + bv1.w; }
        *(float4*)&C[obase + n0 + tx*8    ] = o0;
        *(float4*)&C[obase + n0 + tx*8 + 4] = o1;
    }
}

// ---------------- kernel: two-stream st.async recurrence (R16 champion, verbatim) ----
// 128 CTAs = 16 clusters x 8 CTAs, 256 thr. Cluster cl owns batches [cl*4, cl*4+4):
// stream A = {+0,+1}, stream B = {+2,+3} (independent chains, SAME weight regs).
// Sync: per-(stream,slot) tx-counting mbarrier; st.async self-signaling pushes; no
// fences, no cluster barrier in the loop. xw prefetch right after each wait; push
// before the hs global store (consumers wait on the push, not the STG).
#define CH   36                    // 32 floats + 4 pad per k-slice
#define HB   (2*16*CH)             // 2 batches x 16 slices = 1152 floats per region
#define HB4  (HB*4)                // bytes per region
#define TXB  4096u                 // inbound bytes per mbar phase: 1024 floats

__global__ void __launch_bounds__(256,1) __cluster_dims__(8,1,1)
k_rnn(const float* __restrict__ xw, float* __restrict__ hs,
      const float* __restrict__ Whh, float* __restrict__ hlast){
    __shared__ __align__(16) float sh[4*HB];             // region = stream*2 + slot
    __shared__ __align__(8) ull mb[4];                   // mbar per region
    const int cl   = blockIdx.x >> 3;
    const int rank = blockIdx.x & 7;
    const int tid  = threadIdx.x;
    const int w    = tid >> 5;
    const int lane = tid & 31;
    const int jq   = lane >> 4;
    const int kq   = lane & 15;
    const int j0   = rank*64 + w*8 + jq*4;
    const int bw   = (kq >> 3) & 1;          // batch within stream
    const int j_out= j0 + ((kq >> 1) & 3);
    const int odd  = kq & 1;
    const int bA   = cl*4 + bw;              // absolute batch, stream A output
    const int bB   = cl*4 + 2 + bw;          // absolute batch, stream B output
    const int BH   = Bsz*Hsz;

    // ---- weights: W_hh[j0+jj][kq*32 .. +32) as 16 f32x2 each (serve both streams) ----
    ull w2[4][16];
#pragma unroll
    for (int jj=0;jj<4;jj++){
        const ull* wp = (const ull*)(Whh + (size_t)(j0+jj)*Hsz + kq*32);
#pragma unroll
        for (int i=0;i<16;i++) w2[jj][i] = wp[i];
    }

    // ---- mbar init, cluster-wide visibility, then arm phase 0 of all 4 ----
    const unsigned mb_base = smem_u32(mb);
    if (tid == 0){
#pragma unroll
        for (int i=0;i<4;i++) mbar_init(mb_base + i*8, 1u);
    }
    __syncthreads();
    cluster_arrive(); cluster_wait();        // inits visible before any inbound st.async
    if (tid == 0){
#pragma unroll
        for (int i=0;i<4;i++) mbar_expect(mb_base + i*8, TXB);
    }

    // ---- DSMEM push addresses (data + mbar, SAME 4 ranks) ----
    const unsigned sbase = smem_u32(sh);
    unsigned rsh[4], rmb[4];
#pragma unroll
    for (int r=0;r<4;r++){
        rsh[r] = mapa_rank(sbase,   odd*4 + r);
        rmb[r] = mapa_rank(mb_base, odd*4 + r);
    }
    // consumer layout within a region: ((b*16 + (k>>5))*CH + (k&31)); our k = j_out
    const unsigned inner = (unsigned)(((bw*16 + (j_out>>5))*CH + (j_out&31))*4);

    const float* xwpA = xw + (size_t)bA*Hsz + j_out;
    const float* xwpB = xw + (size_t)bB*Hsz + j_out;
    float*       hspA = hs + (size_t)bA*Hsz + j_out;
    float*       hspB = hs + (size_t)bB*Hsz + j_out;

    const bool hi8 = (lane & 8) != 0;
    const bool hi4 = (lane & 4) != 0;
    const bool hi2 = (lane & 2) != 0;

    // per-stream FMA+reduce over region bi (verified in R7/R10)
    auto stream_mv = [&](int bi)->float{
        const float* buf = sh + bi*HB;
        ull acc[2][4];
#pragma unroll
        for (int b=0;b<2;b++)
#pragma unroll
            for (int jj=0;jj<4;jj++) acc[b][jj] = 0ull;
#pragma unroll
        for (int b=0;b<2;b++){
            const ull* hq = (const ull*)(buf + (b*16 + kq)*CH);
#pragma unroll
            for (int kk=0;kk<16;kk+=2){
                ulonglong2 p = *(const ulonglong2*)&hq[kk];
#pragma unroll
                for (int jj=0;jj<4;jj++){
                    acc[b][jj] = fma2(p.x, w2[jj][kk],   acc[b][jj]);
                    acc[b][jj] = fma2(p.y, w2[jj][kk+1], acc[b][jj]);
                }
            }
        }
        float v[8];
#pragma unroll
        for (int b=0;b<2;b++)
#pragma unroll
            for (int jj=0;jj<4;jj++){
                float l, h; unpack2(acc[b][jj], l, h);
                v[b*4+jj] = l + h;
            }
#pragma unroll
        for (int o=0;o<4;o++){
            float keepv = hi8 ? v[o+4] : v[o];
            float sendv = hi8 ? v[o]   : v[o+4];
            v[o] = keepv + __shfl_xor_sync(0xffffffffu, sendv, 8);
        }
#pragma unroll
        for (int o=0;o<2;o++){
            float keepv = hi4 ? v[o+2] : v[o];
            float sendv = hi4 ? v[o]   : v[o+2];
            v[o] = keepv + __shfl_xor_sync(0xffffffffu, sendv, 4);
        }
        {
            float keepv = hi2 ? v[1] : v[0];
            float sendv = hi2 ? v[0] : v[1];
            v[0] = keepv + __shfl_xor_sync(0xffffffffu, sendv, 2);
        }
        v[0] += __shfl_xor_sync(0xffffffffu, v[0], 1);
        return v[0];
    };

    // push one output to 4 ranks, each store self-signals that rank's region mbar
    auto push_async = [&](float hv, int region){
        unsigned woff = (unsigned)(region*HB4) + inner;
        unsigned moff = (unsigned)(region*8);
#pragma unroll
        for (int r=0;r<4;r++) st_async(rsh[r] + woff, hv, rmb[r] + moff);
    };

    // ---- t = 0 (h_prev = 0) ----
    float xwA = xwpA[0], xwB = xwpB[0];
    {
        float hvA = ftanh(xwA);
        push_async(hvA, 0);                  // stream A, slot 0
        if (!odd) hspA[0] = hvA;
        float hvB = ftanh(xwB);
        push_async(hvB, 2);                  // stream B, slot 0
        if (odd) hspB[0] = hvB;
    }
    xwA = xwpA[BH];  xwB = xwpB[BH];         // prefetch t=1

    for (int t=1;t<Tsz;t++){
        const int m   = (t-1) & 1;                       // mbar/buffer slot of h[t-1]
        const unsigned par = (unsigned)(((t-1) >> 1) & 1);
        const int slot = t & 1;                          // slot for h[t]
        const int toff = t << 15;                        // t*BH

        // ---------- stream A ----------
        mbar_wait(mb_base + (0*2+m)*8, par);             // h[t-1] of A complete
        if (tid == 0 && t <= 509) mbar_expect(mb_base + (0*2+m)*8, TXB);  // arm h[t+1]
        float xwA_n = 0.f;
        if (t != Tsz-1) xwA_n = xwpA[toff + BH];         // prefetch: LDG flies under FMA
        float sumA = stream_mv(0*2 + m);
        float hvA = ftanh(sumA + xwA);
        if (t <= 510) push_async(hvA, 0*2 + slot);       // push FIRST (critical path)
        if (!odd) hspA[toff] = hvA;
        if (t != Tsz-1) xwA = xwA_n;
        else if (!odd)  hlast[bA*Hsz + j_out] = hvA;

        // ---------- stream B ----------
        mbar_wait(mb_base + (1*2+m)*8, par);             // h[t-1] of B complete
        if (tid == 0 && t <= 509) mbar_expect(mb_base + (1*2+m)*8, TXB);
        float xwB_n = 0.f;
        if (t != Tsz-1) xwB_n = xwpB[toff + BH];
        float sumB = stream_mv(1*2 + m);
        float hvB = ftanh(sumB + xwB);
        if (t <= 510) push_async(hvB, 1*2 + slot);
        if (odd) hspB[toff] = hvB;
        if (t != Tsz-1) xwB = xwB_n;
        else if (odd)   hlast[bB*Hsz + j_out] = hvB;
    }
    // no drain needed: t=511 pushed nothing; final waits consumed all inbound tx
}

// ---------------- launch -------------------------------------------------------------
extern "C" void kernel_launch(void* const* d_in, const int* in_sizes, int n_in,
                              void* d_out, int out_size){
    const int*   x    = (const int*)  d_in[0];
    const float* emb  = (const float*)d_in[1];
    const float* Wxh0 = (const float*)d_in[2];
    const float* Whh0 = (const float*)d_in[3];
    const float* bh0  = (const float*)d_in[4];
    const float* Wxh1 = (const float*)d_in[5];
    const float* Whh1 = (const float*)d_in[6];
    const float* bh1  = (const float*)d_in[7];
    const float* Why  = (const float*)d_in[8];
    const float* by   = (const float*)d_in[9];
    float* out = (float*)d_out;

    float *xwbuf, *hs0, *hs1;
    cudaGetSymbolAddress((void**)&xwbuf, g_xw);
    cudaGetSymbolAddress((void**)&hs0,   g_hs0);
    cudaGetSymbolAddress((void**)&hs1,   g_hs1);

    const size_t LOGITS = (size_t)Bsz*Tsz*Vsz;   // 4194304

    dim3 gH(Msz/128, Hsz/128);

    // 1) xw0 = gather(emb, x) @ Wxh0^T + bh0   (gather fused into A-load)
    k_gemm<<<gH, 256>>>(emb, Wxh0, bh0, xwbuf, Msz, Hsz, Esz, 2, x);

    // 2) layer-0 recurrence -> hs0, h_last0
    k_rnn<<<128, 256>>>(xwbuf, hs0, Whh0, out + LOGITS);

    // 3) xw1 = hs0 @ Wxh1^T + bh1
    k_gemm<<<gH, 256>>>(hs0, Wxh1, bh1, xwbuf, Msz, Hsz, Hsz, 0, 0);

    // 4) layer-1 recurrence -> hs1, h_last1
    k_rnn<<<128, 256>>>(xwbuf, hs1, Whh1, out + LOGITS + (size_t)Bsz*Hsz);

    // 5) logits = hs1 @ Why^T + by  (remapped to (b,t,v))
    dim3 gV(Msz/128, Vsz/128);
    k_gemm<<<gV, 256>>>(hs1, Why, by, out, Msz, Vsz, Hsz, 1, 0);
}